// round 1
// baseline (speedup 1.0000x reference)
#include <cuda_runtime.h>
#include <math.h>

#define BB 4
#define NN 32768
#define HH 256
#define SS 64

// ---------------- scratch (static device allocations only) ----------------
__device__ float g_W[(size_t)BB * NN * SS];       // 32 MB soft-assignment weights
__device__ float g_st[BB * SS * HH];              // pooled + gated slice tokens
__device__ float g_qkv[BB * SS * 3 * HH];
__device__ float g_ao[BB * SS * HH];
__device__ float g_st1[BB * SS * HH];
__device__ float g_h[BB * SS * 4 * HH];
__device__ float g_st2[BB * SS * HH];

// ===========================================================================
// K1: fused slot-logits + softmax + pooling.
// grid (128, B), 512 threads, 144KB dyn smem.
// Each block: 256 tokens in 4 tiles of 64. st accumulated in registers across
// tiles (4s x 8h per thread), flushed once with atomicAdd.
// ===========================================================================
__global__ __launch_bounds__(512) void k_assign_pool(
    const float* __restrict__ x, const float* __restrict__ sq_w,
    const float* __restrict__ sq_b) {
  extern __shared__ float sm[];
  float* sqwT = sm;            // [256][64]  sq_w transposed
  float* xt   = sm + 16384;    // [64][256]  x tile
  float* wt   = sm + 32768;    // [64][64]   softmax weights tile

  const int tid = threadIdx.x;
  const int b = blockIdx.y;
  const size_t tok0 = (size_t)blockIdx.x * 256;
  const float* xb = x + (size_t)b * NN * HH;
  float* Wb = g_W + (size_t)b * NN * SS;

  for (int i = tid; i < SS * HH; i += 512) {
    int s = i >> 8, k = i & 255;
    sqwT[k * SS + s] = sq_w[i];
  }

  // phase A mapping: 2 tokens x 4 slots per thread
  const int sgA = tid & 15, tgA = tid >> 4;
  const int t0 = tgA * 2, sA0 = sgA * 4;
  float sb[4];
#pragma unroll
  for (int i = 0; i < 4; i++) sb[i] = sq_b[sA0 + i];

  // phase B mapping: 4 slots x 8 h per thread
  const int hgrp = tid & 31, sgrp = tid >> 5;
  const int h0 = hgrp * 8, sB0 = sgrp * 4;
  float acc[4][8];
#pragma unroll
  for (int i = 0; i < 4; i++)
#pragma unroll
    for (int j = 0; j < 8; j++) acc[i][j] = 0.f;

  __syncthreads();

  for (int tile = 0; tile < 4; ++tile) {
    const size_t n0 = tok0 + tile * 64;
    __syncthreads();  // previous tile's readers of xt/wt done
    for (int i = tid * 4; i < 64 * HH; i += 512 * 4)
      *(float4*)(xt + i) = *(const float4*)(xb + n0 * HH + i);
    __syncthreads();

    // ---- phase A: logits = x . sq_w^T + sq_b ----
    float lg0[4], lg1[4];
#pragma unroll
    for (int i = 0; i < 4; i++) { lg0[i] = sb[i]; lg1[i] = sb[i]; }
    for (int k2 = 0; k2 < HH; k2 += 4) {
      float4 xa = *(const float4*)(xt + t0 * HH + k2);
      float4 xc = *(const float4*)(xt + (t0 + 1) * HH + k2);
      const float* xav = (const float*)&xa;
      const float* xcv = (const float*)&xc;
      const float* wbase = sqwT + k2 * SS + sA0;
#pragma unroll
      for (int j = 0; j < 4; j++) {
        float4 w = *(const float4*)(wbase + j * SS);
        float u = xav[j], v = xcv[j];
        lg0[0] += u * w.x; lg0[1] += u * w.y; lg0[2] += u * w.z; lg0[3] += u * w.w;
        lg1[0] += v * w.x; lg1[1] += v * w.y; lg1[2] += v * w.z; lg1[3] += v * w.w;
      }
    }
    // ---- softmax over 64 slots (16-lane subgroup reduce) ----
    float m0 = fmaxf(fmaxf(lg0[0], lg0[1]), fmaxf(lg0[2], lg0[3]));
    float m1 = fmaxf(fmaxf(lg1[0], lg1[1]), fmaxf(lg1[2], lg1[3]));
#pragma unroll
    for (int off = 8; off; off >>= 1) {
      m0 = fmaxf(m0, __shfl_xor_sync(0xffffffffu, m0, off));
      m1 = fmaxf(m1, __shfl_xor_sync(0xffffffffu, m1, off));
    }
    float e0[4], e1[4], sum0 = 0.f, sum1 = 0.f;
#pragma unroll
    for (int i = 0; i < 4; i++) {
      e0[i] = expf(lg0[i] - m0); sum0 += e0[i];
      e1[i] = expf(lg1[i] - m1); sum1 += e1[i];
    }
#pragma unroll
    for (int off = 8; off; off >>= 1) {
      sum0 += __shfl_xor_sync(0xffffffffu, sum0, off);
      sum1 += __shfl_xor_sync(0xffffffffu, sum1, off);
    }
    float inv0 = 1.f / sum0, inv1 = 1.f / sum1;
    float4 w0 = make_float4(e0[0] * inv0, e0[1] * inv0, e0[2] * inv0, e0[3] * inv0);
    float4 w1 = make_float4(e1[0] * inv1, e1[1] * inv1, e1[2] * inv1, e1[3] * inv1);
    *(float4*)(wt + t0 * SS + sA0) = w0;
    *(float4*)(wt + (t0 + 1) * SS + sA0) = w1;
    *(float4*)(Wb + (n0 + t0) * SS + sA0) = w0;
    *(float4*)(Wb + (n0 + t0 + 1) * SS + sA0) = w1;
    __syncthreads();

    // ---- phase B: st += W^T @ x (register accumulation) ----
    for (int t = 0; t < 64; t++) {
      float4 wv4 = *(const float4*)(wt + t * SS + sB0);
      float4 xA = *(const float4*)(xt + t * HH + h0);
      float4 xB2 = *(const float4*)(xt + t * HH + h0 + 4);
      float wv[4] = {wv4.x, wv4.y, wv4.z, wv4.w};
      float xv[8] = {xA.x, xA.y, xA.z, xA.w, xB2.x, xB2.y, xB2.z, xB2.w};
#pragma unroll
      for (int i = 0; i < 4; i++)
#pragma unroll
        for (int j = 0; j < 8; j++) acc[i][j] += wv[i] * xv[j];
    }
  }

  float* stb = g_st + b * SS * HH;
#pragma unroll
  for (int i = 0; i < 4; i++)
#pragma unroll
    for (int j = 0; j < 8; j++)
      atomicAdd(&stb[(sB0 + i) * HH + h0 + j], acc[i][j]);
}

// ===========================================================================
// Middle stages on [B,S,H] = [4,64,256] — 4 rows per block to amortize
// weight reads, 256 threads.
// ===========================================================================
__global__ __launch_bounds__(256) void k_gate(
    const float* __restrict__ gw, const float* __restrict__ gb,
    const float* __restrict__ estate) {
  int bs0 = blockIdx.x * 4;
  __shared__ float rows[4][256];
  int tid = threadIdx.x;
#pragma unroll
  for (int r = 0; r < 4; r++) rows[r][tid] = g_st[(bs0 + r) * 256 + tid];
  __syncthreads();
  const float* wr = gw + tid * 256;
  float a[4];
#pragma unroll
  for (int r = 0; r < 4; r++) a[r] = gb[tid];
  for (int k2 = 0; k2 < 256; k2 += 4) {
    float4 w = *(const float4*)(wr + k2);
    const float* wv = (const float*)&w;
#pragma unroll
    for (int j = 0; j < 4; j++)
#pragma unroll
      for (int r = 0; r < 4; r++) a[r] += rows[r][k2 + j] * wv[j];
  }
#pragma unroll
  for (int r = 0; r < 4; r++) {
    float gate = 1.f / (1.f + expf(-a[r]));
    int s = (bs0 + r) & 63;
    g_st[(bs0 + r) * 256 + tid] = rows[r][tid] + gate * estate[s * 256 + tid];
  }
}

__global__ __launch_bounds__(256) void k_qkv(
    const float* __restrict__ in_w, const float* __restrict__ in_b) {
  int bs0 = blockIdx.x * 4;
  __shared__ float rows[4][256];
  int tid = threadIdx.x;
#pragma unroll
  for (int r = 0; r < 4; r++) rows[r][tid] = g_st[(bs0 + r) * 256 + tid];
  __syncthreads();
  for (int rc = 0; rc < 3; rc++) {
    int o = rc * 256 + tid;
    const float* wr = in_w + o * 256;
    float a[4];
#pragma unroll
    for (int r = 0; r < 4; r++) a[r] = in_b[o];
    for (int k2 = 0; k2 < 256; k2 += 4) {
      float4 w = *(const float4*)(wr + k2);
      const float* wv = (const float*)&w;
#pragma unroll
      for (int j = 0; j < 4; j++)
#pragma unroll
        for (int r = 0; r < 4; r++) a[r] += rows[r][k2 + j] * wv[j];
    }
#pragma unroll
    for (int r = 0; r < 4; r++) g_qkv[(bs0 + r) * 768 + o] = a[r];
  }
}

__global__ __launch_bounds__(256) void k_attn() {
  int b = blockIdx.x >> 3, hh = blockIdx.x & 7;
  __shared__ float q[64][32], kk[64][33], vv[64][32], p[64][65];
  int tid = threadIdx.x;
  for (int i = tid; i < 2048; i += 256) {
    int s = i >> 5, d = i & 31;
    int base = (b * 64 + s) * 768 + hh * 32 + d;
    q[s][d] = g_qkv[base];
    kk[s][d] = g_qkv[base + 256];
    vv[s][d] = g_qkv[base + 512];
  }
  __syncthreads();
  for (int idx = tid; idx < 4096; idx += 256) {
    int qi = idx >> 6, ki = idx & 63;
    float a = 0.f;
#pragma unroll
    for (int d = 0; d < 32; d++) a += q[qi][d] * kk[ki][d];
    p[qi][ki] = a * 0.17677669529663687f;  // 1/sqrt(32)
  }
  __syncthreads();
  if (tid < 64) {
    float m = -1e30f;
    for (int j = 0; j < 64; j++) m = fmaxf(m, p[tid][j]);
    float ssum = 0.f;
    for (int j = 0; j < 64; j++) { float e = expf(p[tid][j] - m); p[tid][j] = e; ssum += e; }
    float inv = 1.f / ssum;
    for (int j = 0; j < 64; j++) p[tid][j] *= inv;
  }
  __syncthreads();
  for (int idx = tid; idx < 2048; idx += 256) {
    int qi = idx >> 5, d = idx & 31;
    float a = 0.f;
#pragma unroll
    for (int j = 0; j < 64; j++) a += p[qi][j] * vv[j][d];
    g_ao[(b * 64 + qi) * 256 + hh * 32 + d] = a;
  }
}

__device__ __forceinline__ void ln4_reduce(float yv[4], float mu[4], float var[4],
                                           float wsum[4][8], float wsq[4][8],
                                           int tid) {
  float s1[4], s2[4];
#pragma unroll
  for (int r = 0; r < 4; r++) { s1[r] = yv[r]; s2[r] = yv[r] * yv[r]; }
#pragma unroll
  for (int off = 16; off; off >>= 1)
#pragma unroll
    for (int r = 0; r < 4; r++) {
      s1[r] += __shfl_xor_sync(0xffffffffu, s1[r], off);
      s2[r] += __shfl_xor_sync(0xffffffffu, s2[r], off);
    }
  int w = tid >> 5, lane = tid & 31;
  if (lane == 0)
#pragma unroll
    for (int r = 0; r < 4; r++) { wsum[r][w] = s1[r]; wsq[r][w] = s2[r]; }
  __syncthreads();
#pragma unroll
  for (int r = 0; r < 4; r++) {
    float a = 0.f, bq = 0.f;
#pragma unroll
    for (int ww = 0; ww < 8; ww++) { a += wsum[r][ww]; bq += wsq[r][ww]; }
    mu[r] = a * (1.f / 256.f);
    var[r] = bq * (1.f / 256.f) - mu[r] * mu[r];
  }
}

__global__ __launch_bounds__(256) void k_proj_ln1(
    const float* __restrict__ out_w, const float* __restrict__ out_b,
    const float* __restrict__ n1g, const float* __restrict__ n1b) {
  int bs0 = blockIdx.x * 4;
  __shared__ float arow[4][256];
  __shared__ float wsum[4][8], wsq[4][8];
  int tid = threadIdx.x;
#pragma unroll
  for (int r = 0; r < 4; r++) arow[r][tid] = g_ao[(bs0 + r) * 256 + tid];
  __syncthreads();
  const float* wr = out_w + tid * 256;
  float a[4];
#pragma unroll
  for (int r = 0; r < 4; r++) a[r] = out_b[tid];
  for (int k2 = 0; k2 < 256; k2 += 4) {
    float4 w = *(const float4*)(wr + k2);
    const float* wv = (const float*)&w;
#pragma unroll
    for (int j = 0; j < 4; j++)
#pragma unroll
      for (int r = 0; r < 4; r++) a[r] += arow[r][k2 + j] * wv[j];
  }
  float yv[4];
#pragma unroll
  for (int r = 0; r < 4; r++) yv[r] = g_st[(bs0 + r) * 256 + tid] + a[r];
  float mu[4], var[4];
  ln4_reduce(yv, mu, var, wsum, wsq, tid);
#pragma unroll
  for (int r = 0; r < 4; r++)
    g_st1[(bs0 + r) * 256 + tid] =
        (yv[r] - mu[r]) * rsqrtf(var[r] + 1e-5f) * n1g[tid] + n1b[tid];
}

__global__ __launch_bounds__(256) void k_ffn1(
    const float* __restrict__ f1_w, const float* __restrict__ f1_b) {
  int bs0 = blockIdx.x * 4;
  __shared__ float rows[4][256];
  int tid = threadIdx.x;
#pragma unroll
  for (int r = 0; r < 4; r++) rows[r][tid] = g_st1[(bs0 + r) * 256 + tid];
  __syncthreads();
  for (int rc = 0; rc < 4; rc++) {
    int o = rc * 256 + tid;
    const float* wr = f1_w + o * 256;
    float a[4];
#pragma unroll
    for (int r = 0; r < 4; r++) a[r] = f1_b[o];
    for (int k2 = 0; k2 < 256; k2 += 4) {
      float4 w = *(const float4*)(wr + k2);
      const float* wv = (const float*)&w;
#pragma unroll
      for (int j = 0; j < 4; j++)
#pragma unroll
        for (int r = 0; r < 4; r++) a[r] += rows[r][k2 + j] * wv[j];
    }
#pragma unroll
    for (int r = 0; r < 4; r++) {
      float v = a[r];
      g_h[(bs0 + r) * 1024 + o] = 0.5f * v * (1.f + erff(v * 0.7071067811865475f));
    }
  }
}

__global__ __launch_bounds__(256) void k_ffn2_ln2(
    const float* __restrict__ f2_w, const float* __restrict__ f2_b,
    const float* __restrict__ n2g, const float* __restrict__ n2b) {
  int bs0 = blockIdx.x * 4;
  __shared__ float hrow[4][1024];
  __shared__ float wsum[4][8], wsq[4][8];
  int tid = threadIdx.x;
  for (int i = tid; i < 4096; i += 256) {
    int r = i >> 10, c = i & 1023;
    hrow[r][c] = g_h[(bs0 + r) * 1024 + c];
  }
  __syncthreads();
  const float* wr = f2_w + tid * 1024;
  float a[4];
#pragma unroll
  for (int r = 0; r < 4; r++) a[r] = f2_b[tid];
  for (int k2 = 0; k2 < 1024; k2 += 4) {
    float4 w = *(const float4*)(wr + k2);
    const float* wv = (const float*)&w;
#pragma unroll
    for (int j = 0; j < 4; j++)
#pragma unroll
      for (int r = 0; r < 4; r++) a[r] += hrow[r][k2 + j] * wv[j];
  }
  float yv[4];
#pragma unroll
  for (int r = 0; r < 4; r++) yv[r] = g_st1[(bs0 + r) * 256 + tid] + a[r];
  float mu[4], var[4];
  ln4_reduce(yv, mu, var, wsum, wsq, tid);
#pragma unroll
  for (int r = 0; r < 4; r++)
    g_st2[(bs0 + r) * 256 + tid] =
        (yv[r] - mu[r]) * rsqrtf(var[r] + 1e-5f) * n2g[tid] + n2b[tid];
}

// ===========================================================================
// K3: decode out = W @ st2 + x.  grid (256, B), 256 threads, ~73KB smem.
// Each block: 128 tokens in 4 chunks of 32; st2 staged once.
// ===========================================================================
__global__ __launch_bounds__(256) void k_decode(const float* __restrict__ x,
                                                float* __restrict__ out) {
  extern __shared__ float sm[];
  float* st2s = sm;           // [64][256]
  float* Wt = sm + 16384;     // [64][36] padded, transposed W chunk
  const int tid = threadIdx.x;
  const int b = blockIdx.y;
  for (int i = tid * 4; i < 16384; i += 1024)
    *(float4*)(st2s + i) = *(const float4*)(g_st2 + b * 16384 + i);
  const int hgrp = tid & 31, tgrp = tid >> 5;
  const int h0 = hgrp * 8, tl0 = tgrp * 4;
  const float* Wb = g_W + (size_t)b * NN * SS;

  for (int chunk = 0; chunk < 4; chunk++) {
    const size_t n0 = (size_t)blockIdx.x * 128 + chunk * 32;
    __syncthreads();
    for (int i = tid; i < 2048; i += 256) {
      int t = i >> 6, s2 = i & 63;
      Wt[s2 * 36 + t] = Wb[(n0 + t) * SS + s2];
    }
    __syncthreads();
    float acc[4][8];
#pragma unroll
    for (int i = 0; i < 4; i++)
#pragma unroll
      for (int j = 0; j < 8; j++) acc[i][j] = 0.f;
    for (int s2 = 0; s2 < 64; s2++) {
      float4 w4 = *(const float4*)(Wt + s2 * 36 + tl0);
      float4 xA = *(const float4*)(st2s + s2 * 256 + h0);
      float4 xB2 = *(const float4*)(st2s + s2 * 256 + h0 + 4);
      float wv[4] = {w4.x, w4.y, w4.z, w4.w};
      float xv[8] = {xA.x, xA.y, xA.z, xA.w, xB2.x, xB2.y, xB2.z, xB2.w};
#pragma unroll
      for (int i = 0; i < 4; i++)
#pragma unroll
        for (int j = 0; j < 8; j++) acc[i][j] += wv[i] * xv[j];
    }
#pragma unroll
    for (int i = 0; i < 4; i++) {
      size_t base = ((size_t)b * NN + n0 + tl0 + i) * HH + h0;
      float4 xv1 = *(const float4*)(x + base);
      float4 xv2 = *(const float4*)(x + base + 4);
      float4 o1 = make_float4(acc[i][0] + xv1.x, acc[i][1] + xv1.y,
                              acc[i][2] + xv1.z, acc[i][3] + xv1.w);
      float4 o2 = make_float4(acc[i][4] + xv2.x, acc[i][5] + xv2.y,
                              acc[i][6] + xv2.z, acc[i][7] + xv2.w);
      *(float4*)(out + base) = o1;
      *(float4*)(out + base + 4) = o2;
    }
  }
}

// ===========================================================================
extern "C" void kernel_launch(void* const* d_in, const int* in_sizes, int n_in,
                              void* d_out, int out_size) {
  const float* x = (const float*)d_in[0];
  const float* sq_w = (const float*)d_in[1];
  const float* sq_b = (const float*)d_in[2];
  const float* eid_state = (const float*)d_in[3];
  const float* eid_gw = (const float*)d_in[4];
  const float* eid_gb = (const float*)d_in[5];
  const float* in_w = (const float*)d_in[6];
  const float* in_b = (const float*)d_in[7];
  const float* out_w = (const float*)d_in[8];
  const float* out_b = (const float*)d_in[9];
  const float* n1_g = (const float*)d_in[10];
  const float* n1_b = (const float*)d_in[11];
  const float* n2_g = (const float*)d_in[12];
  const float* n2_b = (const float*)d_in[13];
  const float* f1_w = (const float*)d_in[14];
  const float* f1_b = (const float*)d_in[15];
  const float* f2_w = (const float*)d_in[16];
  const float* f2_b = (const float*)d_in[17];
  float* out = (float*)d_out;

  void* stp = 0;
  cudaGetSymbolAddress(&stp, g_st);
  cudaMemsetAsync(stp, 0, (size_t)BB * SS * HH * sizeof(float));

  cudaFuncSetAttribute(k_assign_pool, cudaFuncAttributeMaxDynamicSharedMemorySize,
                       147456);
  cudaFuncSetAttribute(k_decode, cudaFuncAttributeMaxDynamicSharedMemorySize,
                       74752);

  k_assign_pool<<<dim3(128, BB), 512, 147456>>>(x, sq_w, sq_b);
  k_gate<<<64, 256>>>(eid_gw, eid_gb, eid_state);
  k_qkv<<<64, 256>>>(in_w, in_b);
  k_attn<<<32, 256>>>();
  k_proj_ln1<<<64, 256>>>(out_w, out_b, n1_g, n1_b);
  k_ffn1<<<64, 256>>>(f1_w, f1_b);
  k_ffn2_ln2<<<64, 256>>>(f2_w, f2_b, n2_g, n2_b);
  k_decode<<<dim3(256, BB), 256, 74752>>>(x, out);
}

// round 4
// speedup vs baseline: 1.5335x; 1.5335x over previous
#include <cuda_runtime.h>
#include <stdint.h>
#include <math.h>

#define BB 4
#define NN 32768
#define HH 256
#define SS 64

#define XP 268   // xs row pad (floats)
#define WP 268   // sq_w row pad
#define LP 72    // logits/W tile row pad
#define SP 268   // st2 row pad (KC)
#define AP 68    // W tile row pad (KC)

// ---------------- scratch (static device allocations only) ----------------
__device__ float g_W[(size_t)BB * NN * SS];          // 32 MB soft-assignment weights
__device__ float g_part[(size_t)512 * 16384];        // 33.5MB pooling partials
__device__ float g_st[BB * SS * HH];
__device__ float g_qkv[BB * SS * 3 * HH];
__device__ float g_ao[BB * SS * HH];
__device__ float g_st1[BB * SS * HH];
__device__ float g_h[BB * SS * 4 * HH];
__device__ float g_st2[BB * SS * HH];

// ---- m16n8k8 tf32 mma helper --------------------------------------------
__device__ __forceinline__ void mma_tf32(float c[4], uint32_t a0, uint32_t a1,
                                         uint32_t a2, uint32_t a3, uint32_t b0,
                                         uint32_t b1) {
  asm volatile(
      "mma.sync.aligned.m16n8k8.row.col.f32.tf32.tf32.f32 "
      "{%0,%1,%2,%3}, {%4,%5,%6,%7}, {%8,%9}, {%0,%1,%2,%3};\n"
      : "+f"(c[0]), "+f"(c[1]), "+f"(c[2]), "+f"(c[3])
      : "r"(a0), "r"(a1), "r"(a2), "r"(a3), "r"(b0), "r"(b1));
}
#define F2U __float_as_uint

// ===========================================================================
// KA: fused logits(tf32 mma) + softmax + pooling(tf32 mma, transposed output)
// grid (128, B), 256 threads (8 warps). 256 tokens per block in 4 tiles of 64.
// Pooling partial st^T accumulated in registers, flushed to g_part.
// ===========================================================================
__global__ __launch_bounds__(256) void k_assign_pool(
    const float* __restrict__ x, const float* __restrict__ sq_w,
    const float* __restrict__ sq_b) {
  extern __shared__ float sm[];
  float* xs = sm;                 // [64][XP]
  float* ws = sm + 64 * XP;       // [64][WP]
  float* lg = ws + 64 * WP;       // [64][LP]
  float* sb = lg + 64 * LP;       // [64]

  const int tid = threadIdx.x;
  const int b = blockIdx.y;
  const size_t tok0 = (size_t)blockIdx.x * 256;
  const float* xb = x + (size_t)b * NN * HH;

  // load sq_w (padded) + bias
  for (int i = tid * 4; i < 64 * 256; i += 1024) {
    float4 v = *(const float4*)(sq_w + i);
    *(float4*)(ws + (i >> 8) * WP + (i & 255)) = v;
  }
  if (tid < 64) sb[tid] = sq_b[tid];

  const int wid = tid >> 5, lane = tid & 31;
  const int r = lane >> 2, q = lane & 3;
  const int mA = (wid & 3) * 16;   // phase-A token m-tile base
  const int kh = (wid >> 2) * 128; // phase-A k half
  const int hb = wid * 32;         // pooling h base (2 m-tiles of 16)

  float stacc[2][8][4];
#pragma unroll
  for (int i = 0; i < 2; i++)
#pragma unroll
    for (int j = 0; j < 8; j++)
#pragma unroll
      for (int k = 0; k < 4; k++) stacc[i][j][k] = 0.f;

  for (int tile = 0; tile < 4; tile++) {
    __syncthreads();  // xs/lg consumers from previous tile done (also covers ws)
    const float* xsrc = xb + (tok0 + tile * 64) * 256;
    for (int i = tid * 4; i < 16384; i += 1024)
      *(float4*)(xs + (i >> 8) * XP + (i & 255)) = *(const float4*)(xsrc + i);
    __syncthreads();

    // ---- phase A: logits[tok][slot] via mma, split-K across warp halves ----
    float lacc[8][4];
#pragma unroll
    for (int j = 0; j < 8; j++)
#pragma unroll
      for (int k = 0; k < 4; k++) lacc[j][k] = 0.f;

    for (int ks = 0; ks < 16; ks++) {
      const int k0 = kh + ks * 8;
      uint32_t a0 = F2U(xs[(mA + r) * XP + k0 + q]);
      uint32_t a1 = F2U(xs[(mA + r + 8) * XP + k0 + q]);
      uint32_t a2 = F2U(xs[(mA + r) * XP + k0 + q + 4]);
      uint32_t a3 = F2U(xs[(mA + r + 8) * XP + k0 + q + 4]);
#pragma unroll
      for (int nt = 0; nt < 8; nt++) {
        uint32_t b0 = F2U(ws[(nt * 8 + r) * WP + k0 + q]);
        uint32_t b1 = F2U(ws[(nt * 8 + r) * WP + k0 + q + 4]);
        mma_tf32(lacc[nt], a0, a1, a2, a3, b0, b1);
      }
    }
    // reduce the two k-halves into lg
    if ((wid >> 2) == 0) {
#pragma unroll
      for (int nt = 0; nt < 8; nt++) {
        lg[(mA + r) * LP + nt * 8 + 2 * q] = lacc[nt][0];
        lg[(mA + r) * LP + nt * 8 + 2 * q + 1] = lacc[nt][1];
        lg[(mA + r + 8) * LP + nt * 8 + 2 * q] = lacc[nt][2];
        lg[(mA + r + 8) * LP + nt * 8 + 2 * q + 1] = lacc[nt][3];
      }
    }
    __syncthreads();
    if ((wid >> 2) == 1) {
#pragma unroll
      for (int nt = 0; nt < 8; nt++) {
        lg[(mA + r) * LP + nt * 8 + 2 * q] += lacc[nt][0];
        lg[(mA + r) * LP + nt * 8 + 2 * q + 1] += lacc[nt][1];
        lg[(mA + r + 8) * LP + nt * 8 + 2 * q] += lacc[nt][2];
        lg[(mA + r + 8) * LP + nt * 8 + 2 * q + 1] += lacc[nt][3];
      }
    }
    __syncthreads();

    // ---- softmax: 4 threads per row ----
    {
      const int t = tid >> 2, qq = tid & 3;
      float v[16];
      float mx = -1e30f;
#pragma unroll
      for (int i = 0; i < 16; i++) {
        v[i] = lg[t * LP + qq * 16 + i] + sb[qq * 16 + i];
        mx = fmaxf(mx, v[i]);
      }
      mx = fmaxf(mx, __shfl_xor_sync(0xffffffffu, mx, 1));
      mx = fmaxf(mx, __shfl_xor_sync(0xffffffffu, mx, 2));
      float s = 0.f;
#pragma unroll
      for (int i = 0; i < 16; i++) {
        v[i] = __expf(v[i] - mx);
        s += v[i];
      }
      s += __shfl_xor_sync(0xffffffffu, s, 1);
      s += __shfl_xor_sync(0xffffffffu, s, 2);
      const float inv = 1.f / s;
      const size_t wrow =
          ((size_t)b * NN + tok0 + tile * 64 + t) * 64 + qq * 16;
#pragma unroll
      for (int i = 0; i < 16; i++) {
        float w = v[i] * inv;
        lg[t * LP + qq * 16 + i] = w;
        g_W[wrow + i] = w;
      }
    }
    __syncthreads();

    // ---- pooling: st^T[h][s] += x^T @ Wtile ----
    for (int ks = 0; ks < 8; ks++) {
      const int k0 = ks * 8;
      uint32_t a[2][4];
#pragma unroll
      for (int mt = 0; mt < 2; mt++) {
        const int h0 = hb + mt * 16;
        a[mt][0] = F2U(xs[(k0 + q) * XP + h0 + r]);
        a[mt][1] = F2U(xs[(k0 + q) * XP + h0 + r + 8]);
        a[mt][2] = F2U(xs[(k0 + q + 4) * XP + h0 + r]);
        a[mt][3] = F2U(xs[(k0 + q + 4) * XP + h0 + r + 8]);
      }
#pragma unroll
      for (int nt = 0; nt < 8; nt++) {
        uint32_t b0 = F2U(lg[(k0 + q) * LP + nt * 8 + r]);
        uint32_t b1 = F2U(lg[(k0 + q + 4) * LP + nt * 8 + r]);
        mma_tf32(stacc[0][nt], a[0][0], a[0][1], a[0][2], a[0][3], b0, b1);
        mma_tf32(stacc[1][nt], a[1][0], a[1][1], a[1][2], a[1][3], b0, b1);
      }
    }
  }

  // flush partials
  float* pp = g_part + (size_t)(b * 128 + blockIdx.x) * 16384;
#pragma unroll
  for (int mt = 0; mt < 2; mt++) {
#pragma unroll
    for (int nt = 0; nt < 8; nt++) {
      const int h0 = hb + mt * 16 + r;
      const int s0 = nt * 8 + 2 * q;
      *(float2*)(pp + h0 * 64 + s0) =
          make_float2(stacc[mt][nt][0], stacc[mt][nt][1]);
      *(float2*)(pp + (h0 + 8) * 64 + s0) =
          make_float2(stacc[mt][nt][2], stacc[mt][nt][3]);
    }
  }
}

// ===========================================================================
// reduce pooling partials -> g_st (standard [b][s][h] layout)
// ===========================================================================
__global__ __launch_bounds__(256) void k_reduce_st() {
  const int gt = blockIdx.x * 256 + threadIdx.x;  // 0..32767
  const int bh = gt >> 14;                        // 0..1
  const int pos = gt & 16383;
#pragma unroll
  for (int bi = 0; bi < 2; bi++) {
    const int bb = bh * 2 + bi;
    const float* p = g_part + (size_t)bb * 128 * 16384 + pos;
    float acc = 0.f;
#pragma unroll 4
    for (int j = 0; j < 128; j++) acc += p[(size_t)j * 16384];
    const int h = pos >> 6, s = pos & 63;
    g_st[bb * 16384 + s * 256 + h] = acc;
  }
}

// ===========================================================================
// Middle stages on [B,S,H] = [4,64,256]
// ===========================================================================
__global__ __launch_bounds__(256) void k_gate(
    const float* __restrict__ gw, const float* __restrict__ gb,
    const float* __restrict__ estate) {
  int bs0 = blockIdx.x * 4;
  __shared__ float rows[4][256];
  int tid = threadIdx.x;
#pragma unroll
  for (int r = 0; r < 4; r++) rows[r][tid] = g_st[(bs0 + r) * 256 + tid];
  __syncthreads();
  const float* wr = gw + tid * 256;
  float a[4];
#pragma unroll
  for (int r = 0; r < 4; r++) a[r] = gb[tid];
  for (int k2 = 0; k2 < 256; k2 += 4) {
    float4 w = *(const float4*)(wr + k2);
    const float* wv = (const float*)&w;
#pragma unroll
    for (int j = 0; j < 4; j++)
#pragma unroll
      for (int r = 0; r < 4; r++) a[r] += rows[r][k2 + j] * wv[j];
  }
#pragma unroll
  for (int r = 0; r < 4; r++) {
    float gate = 1.f / (1.f + expf(-a[r]));
    int s = (bs0 + r) & 63;
    g_st[(bs0 + r) * 256 + tid] = rows[r][tid] + gate * estate[s * 256 + tid];
  }
}

__global__ __launch_bounds__(256) void k_qkv(
    const float* __restrict__ in_w, const float* __restrict__ in_b) {
  int bs0 = blockIdx.x * 4;
  __shared__ float rows[4][256];
  int tid = threadIdx.x;
#pragma unroll
  for (int r = 0; r < 4; r++) rows[r][tid] = g_st[(bs0 + r) * 256 + tid];
  __syncthreads();
  for (int rc = 0; rc < 3; rc++) {
    int o = rc * 256 + tid;
    const float* wr = in_w + o * 256;
    float a[4];
#pragma unroll
    for (int r = 0; r < 4; r++) a[r] = in_b[o];
    for (int k2 = 0; k2 < 256; k2 += 4) {
      float4 w = *(const float4*)(wr + k2);
      const float* wv = (const float*)&w;
#pragma unroll
      for (int j = 0; j < 4; j++)
#pragma unroll
        for (int r = 0; r < 4; r++) a[r] += rows[r][k2 + j] * wv[j];
    }
#pragma unroll
    for (int r = 0; r < 4; r++) g_qkv[(bs0 + r) * 768 + o] = a[r];
  }
}

__global__ __launch_bounds__(256) void k_attn() {
  int b = blockIdx.x >> 3, hh = blockIdx.x & 7;
  __shared__ float q[64][32], kk[64][33], vv[64][32], p[64][65];
  int tid = threadIdx.x;
  for (int i = tid; i < 2048; i += 256) {
    int s = i >> 5, d = i & 31;
    int base = (b * 64 + s) * 768 + hh * 32 + d;
    q[s][d] = g_qkv[base];
    kk[s][d] = g_qkv[base + 256];
    vv[s][d] = g_qkv[base + 512];
  }
  __syncthreads();
  for (int idx = tid; idx < 4096; idx += 256) {
    int qi = idx >> 6, ki = idx & 63;
    float a = 0.f;
#pragma unroll
    for (int d = 0; d < 32; d++) a += q[qi][d] * kk[ki][d];
    p[qi][ki] = a * 0.17677669529663687f;
  }
  __syncthreads();
  if (tid < 64) {
    float m = -1e30f;
    for (int j = 0; j < 64; j++) m = fmaxf(m, p[tid][j]);
    float ssum = 0.f;
    for (int j = 0; j < 64; j++) { float e = expf(p[tid][j] - m); p[tid][j] = e; ssum += e; }
    float inv = 1.f / ssum;
    for (int j = 0; j < 64; j++) p[tid][j] *= inv;
  }
  __syncthreads();
  for (int idx = tid; idx < 2048; idx += 256) {
    int qi = idx >> 5, d = idx & 31;
    float a = 0.f;
#pragma unroll
    for (int j = 0; j < 64; j++) a += p[qi][j] * vv[j][d];
    g_ao[(b * 64 + qi) * 256 + hh * 32 + d] = a;
  }
}

__device__ __forceinline__ void ln4_reduce(float yv[4], float mu[4], float var[4],
                                           float wsum[4][8], float wsq[4][8],
                                           int tid) {
  float s1[4], s2[4];
#pragma unroll
  for (int r = 0; r < 4; r++) { s1[r] = yv[r]; s2[r] = yv[r] * yv[r]; }
#pragma unroll
  for (int off = 16; off; off >>= 1)
#pragma unroll
    for (int r = 0; r < 4; r++) {
      s1[r] += __shfl_xor_sync(0xffffffffu, s1[r], off);
      s2[r] += __shfl_xor_sync(0xffffffffu, s2[r], off);
    }
  int w = tid >> 5, lane = tid & 31;
  if (lane == 0)
#pragma unroll
    for (int r = 0; r < 4; r++) { wsum[r][w] = s1[r]; wsq[r][w] = s2[r]; }
  __syncthreads();
#pragma unroll
  for (int r = 0; r < 4; r++) {
    float a = 0.f, bq = 0.f;
#pragma unroll
    for (int ww = 0; ww < 8; ww++) { a += wsum[r][ww]; bq += wsq[r][ww]; }
    mu[r] = a * (1.f / 256.f);
    var[r] = bq * (1.f / 256.f) - mu[r] * mu[r];
  }
}

__global__ __launch_bounds__(256) void k_proj_ln1(
    const float* __restrict__ out_w, const float* __restrict__ out_b,
    const float* __restrict__ n1g, const float* __restrict__ n1b) {
  int bs0 = blockIdx.x * 4;
  __shared__ float arow[4][256];
  __shared__ float wsum[4][8], wsq[4][8];
  int tid = threadIdx.x;
#pragma unroll
  for (int r = 0; r < 4; r++) arow[r][tid] = g_ao[(bs0 + r) * 256 + tid];
  __syncthreads();
  const float* wr = out_w + tid * 256;
  float a[4];
#pragma unroll
  for (int r = 0; r < 4; r++) a[r] = out_b[tid];
  for (int k2 = 0; k2 < 256; k2 += 4) {
    float4 w = *(const float4*)(wr + k2);
    const float* wv = (const float*)&w;
#pragma unroll
    for (int j = 0; j < 4; j++)
#pragma unroll
      for (int r = 0; r < 4; r++) a[r] += arow[r][k2 + j] * wv[j];
  }
  float yv[4];
#pragma unroll
  for (int r = 0; r < 4; r++) yv[r] = g_st[(bs0 + r) * 256 + tid] + a[r];
  float mu[4], var[4];
  ln4_reduce(yv, mu, var, wsum, wsq, tid);
#pragma unroll
  for (int r = 0; r < 4; r++)
    g_st1[(bs0 + r) * 256 + tid] =
        (yv[r] - mu[r]) * rsqrtf(var[r] + 1e-5f) * n1g[tid] + n1b[tid];
}

__global__ __launch_bounds__(256) void k_ffn1(
    const float* __restrict__ f1_w, const float* __restrict__ f1_b) {
  int bs0 = blockIdx.x * 4;
  __shared__ float rows[4][256];
  int tid = threadIdx.x;
#pragma unroll
  for (int r = 0; r < 4; r++) rows[r][tid] = g_st1[(bs0 + r) * 256 + tid];
  __syncthreads();
  for (int rc = 0; rc < 4; rc++) {
    int o = rc * 256 + tid;
    const float* wr = f1_w + o * 256;
    float a[4];
#pragma unroll
    for (int r = 0; r < 4; r++) a[r] = f1_b[o];
    for (int k2 = 0; k2 < 256; k2 += 4) {
      float4 w = *(const float4*)(wr + k2);
      const float* wv = (const float*)&w;
#pragma unroll
      for (int j = 0; j < 4; j++)
#pragma unroll
        for (int r = 0; r < 4; r++) a[r] += rows[r][k2 + j] * wv[j];
    }
#pragma unroll
    for (int r = 0; r < 4; r++) {
      float v = a[r];
      g_h[(bs0 + r) * 1024 + o] = 0.5f * v * (1.f + erff(v * 0.7071067811865475f));
    }
  }
}

__global__ __launch_bounds__(256) void k_ffn2_ln2(
    const float* __restrict__ f2_w, const float* __restrict__ f2_b,
    const float* __restrict__ n2g, const float* __restrict__ n2b) {
  int bs0 = blockIdx.x * 4;
  __shared__ float hrow[4][1024];
  __shared__ float wsum[4][8], wsq[4][8];
  int tid = threadIdx.x;
  for (int i = tid; i < 4096; i += 256) {
    int r = i >> 10, c = i & 1023;
    hrow[r][c] = g_h[(bs0 + r) * 1024 + c];
  }
  __syncthreads();
  const float* wr = f2_w + tid * 1024;
  float a[4];
#pragma unroll
  for (int r = 0; r < 4; r++) a[r] = f2_b[tid];
  for (int k2 = 0; k2 < 1024; k2 += 4) {
    float4 w = *(const float4*)(wr + k2);
    const float* wv = (const float*)&w;
#pragma unroll
    for (int j = 0; j < 4; j++)
#pragma unroll
      for (int r = 0; r < 4; r++) a[r] += hrow[r][k2 + j] * wv[j];
  }
  float yv[4];
#pragma unroll
  for (int r = 0; r < 4; r++) yv[r] = g_st1[(bs0 + r) * 256 + tid] + a[r];
  float mu[4], var[4];
  ln4_reduce(yv, mu, var, wsum, wsq, tid);
#pragma unroll
  for (int r = 0; r < 4; r++)
    g_st2[(bs0 + r) * 256 + tid] =
        (yv[r] - mu[r]) * rsqrtf(var[r] + 1e-5f) * n2g[tid] + n2b[tid];
}

// ===========================================================================
// KC: decode out = W @ st2 + x via tf32 mma. grid (256, B), 256 threads.
// ===========================================================================
__global__ __launch_bounds__(256) void k_decode(const float* __restrict__ x,
                                                float* __restrict__ out) {
  extern __shared__ float sm[];
  float* st2s = sm;              // [64][SP]
  float* Ws = sm + 64 * SP;      // [128][AP]
  const int tid = threadIdx.x;
  const int b = blockIdx.y;
  const int n0 = blockIdx.x * 128;

  for (int i = tid * 4; i < 16384; i += 1024)
    *(float4*)(st2s + (i >> 8) * SP + (i & 255)) =
        *(const float4*)(g_st2 + b * 16384 + i);
  for (int i = tid * 4; i < 8192; i += 1024)
    *(float4*)(Ws + (i >> 6) * AP + (i & 63)) =
        *(const float4*)(g_W + ((size_t)b * NN + n0 + (i >> 6)) * 64 + (i & 63));
  __syncthreads();

  const int wid = tid >> 5, lane = tid & 31;
  const int r = lane >> 2, q = lane & 3;
  const int m0 = wid * 16;

  for (int nh = 0; nh < 2; nh++) {
    float acc[16][4];
#pragma unroll
    for (int i = 0; i < 16; i++)
#pragma unroll
      for (int j = 0; j < 4; j++) acc[i][j] = 0.f;

    for (int ks = 0; ks < 8; ks++) {
      const int k0 = ks * 8;
      uint32_t a0 = F2U(Ws[(m0 + r) * AP + k0 + q]);
      uint32_t a1 = F2U(Ws[(m0 + r + 8) * AP + k0 + q]);
      uint32_t a2 = F2U(Ws[(m0 + r) * AP + k0 + q + 4]);
      uint32_t a3 = F2U(Ws[(m0 + r + 8) * AP + k0 + q + 4]);
#pragma unroll
      for (int nt = 0; nt < 16; nt++) {
        const int n = nh * 128 + nt * 8;
        uint32_t b0 = F2U(st2s[(k0 + q) * SP + n + r]);
        uint32_t b1 = F2U(st2s[(k0 + q + 4) * SP + n + r]);
        mma_tf32(acc[nt], a0, a1, a2, a3, b0, b1);
      }
    }
#pragma unroll
    for (int nt = 0; nt < 16; nt++) {
      const int n = nh * 128 + nt * 8 + 2 * q;
      const size_t base0 = ((size_t)b * NN + n0 + m0 + r) * 256 + n;
      const size_t base1 = base0 + 8 * 256;
      float2 xv0 = *(const float2*)(x + base0);
      float2 xv1 = *(const float2*)(x + base1);
      *(float2*)(out + base0) = make_float2(acc[nt][0] + xv0.x, acc[nt][1] + xv0.y);
      *(float2*)(out + base1) = make_float2(acc[nt][2] + xv1.x, acc[nt][3] + xv1.y);
    }
  }
}

// ===========================================================================
extern "C" void kernel_launch(void* const* d_in, const int* in_sizes, int n_in,
                              void* d_out, int out_size) {
  const float* x = (const float*)d_in[0];
  const float* sq_w = (const float*)d_in[1];
  const float* sq_b = (const float*)d_in[2];
  const float* eid_state = (const float*)d_in[3];
  const float* eid_gw = (const float*)d_in[4];
  const float* eid_gb = (const float*)d_in[5];
  const float* in_w = (const float*)d_in[6];
  const float* in_b = (const float*)d_in[7];
  const float* out_w = (const float*)d_in[8];
  const float* out_b = (const float*)d_in[9];
  const float* n1_g = (const float*)d_in[10];
  const float* n1_b = (const float*)d_in[11];
  const float* n2_g = (const float*)d_in[12];
  const float* n2_b = (const float*)d_in[13];
  const float* f1_w = (const float*)d_in[14];
  const float* f1_b = (const float*)d_in[15];
  const float* f2_w = (const float*)d_in[16];
  const float* f2_b = (const float*)d_in[17];
  float* out = (float*)d_out;

  const int smem_ka = (64 * XP + 64 * WP + 64 * LP + 64) * 4;
  const int smem_kc = (64 * SP + 128 * AP) * 4;
  cudaFuncSetAttribute(k_assign_pool, cudaFuncAttributeMaxDynamicSharedMemorySize,
                       smem_ka);
  cudaFuncSetAttribute(k_decode, cudaFuncAttributeMaxDynamicSharedMemorySize,
                       smem_kc);

  k_assign_pool<<<dim3(128, BB), 256, smem_ka>>>(x, sq_w, sq_b);
  k_reduce_st<<<128, 256>>>();
  k_gate<<<64, 256>>>(eid_gw, eid_gb, eid_state);
  k_qkv<<<64, 256>>>(in_w, in_b);
  k_attn<<<32, 256>>>();
  k_proj_ln1<<<64, 256>>>(out_w, out_b, n1_g, n1_b);
  k_ffn1<<<64, 256>>>(f1_w, f1_b);
  k_ffn2_ln2<<<64, 256>>>(f2_w, f2_b, n2_g, n2_b);
  k_decode<<<dim3(256, BB), 256, smem_kc>>>(x, out);
}

// round 5
// speedup vs baseline: 1.6531x; 1.0780x over previous
#include <cuda_runtime.h>
#include <stdint.h>
#include <math.h>

#define BB 4
#define NN 32768
#define HH 256
#define SS 64

#define XP 268   // xs row pad (floats)
#define WP 268   // sq_w row pad
#define LP 72    // logits/W tile row pad
#define SP 268   // st2 row pad (KC)
#define AP 68    // W tile row pad (KC)

// ---------------- scratch (static device allocations only) ----------------
__device__ float g_W[(size_t)BB * NN * SS];          // 32 MB soft-assignment weights
__device__ float g_part[(size_t)512 * 16384];        // 33.5MB pooling partials
__device__ float g_st[BB * SS * HH];
__device__ float g_stg[BB * SS * HH];                // gated st
__device__ float g_qkv[BB * SS * 3 * HH];
__device__ float g_ao[BB * SS * HH];
__device__ float g_pro[BB * SS * HH];                // attn out-proj (pre-LN)
__device__ float g_st1[BB * SS * HH];
__device__ float g_h[BB * SS * 4 * HH];
__device__ float g_f2p[2][BB * SS * HH];             // ffn2 k-split partials
__device__ float g_st2[BB * SS * HH];

// ---- m16n8k8 tf32 mma helper --------------------------------------------
__device__ __forceinline__ void mma_tf32(float c[4], uint32_t a0, uint32_t a1,
                                         uint32_t a2, uint32_t a3, uint32_t b0,
                                         uint32_t b1) {
  asm volatile(
      "mma.sync.aligned.m16n8k8.row.col.f32.tf32.tf32.f32 "
      "{%0,%1,%2,%3}, {%4,%5,%6,%7}, {%8,%9}, {%0,%1,%2,%3};\n"
      : "+f"(c[0]), "+f"(c[1]), "+f"(c[2]), "+f"(c[3])
      : "r"(a0), "r"(a1), "r"(a2), "r"(a3), "r"(b0), "r"(b1));
}
#define F2U __float_as_uint

// ===========================================================================
// KA: fused logits(tf32 mma) + softmax + pooling (unchanged from R4)
// ===========================================================================
__global__ __launch_bounds__(256) void k_assign_pool(
    const float* __restrict__ x, const float* __restrict__ sq_w,
    const float* __restrict__ sq_b) {
  extern __shared__ float sm[];
  float* xs = sm;                 // [64][XP]
  float* ws = sm + 64 * XP;       // [64][WP]
  float* lg = ws + 64 * WP;       // [64][LP]
  float* sb = lg + 64 * LP;       // [64]

  const int tid = threadIdx.x;
  const int b = blockIdx.y;
  const size_t tok0 = (size_t)blockIdx.x * 256;
  const float* xb = x + (size_t)b * NN * HH;

  for (int i = tid * 4; i < 64 * 256; i += 1024) {
    float4 v = *(const float4*)(sq_w + i);
    *(float4*)(ws + (i >> 8) * WP + (i & 255)) = v;
  }
  if (tid < 64) sb[tid] = sq_b[tid];

  const int wid = tid >> 5, lane = tid & 31;
  const int r = lane >> 2, q = lane & 3;
  const int mA = (wid & 3) * 16;
  const int kh = (wid >> 2) * 128;
  const int hb = wid * 32;

  float stacc[2][8][4];
#pragma unroll
  for (int i = 0; i < 2; i++)
#pragma unroll
    for (int j = 0; j < 8; j++)
#pragma unroll
      for (int k = 0; k < 4; k++) stacc[i][j][k] = 0.f;

  for (int tile = 0; tile < 4; tile++) {
    __syncthreads();
    const float* xsrc = xb + (tok0 + tile * 64) * 256;
    for (int i = tid * 4; i < 16384; i += 1024)
      *(float4*)(xs + (i >> 8) * XP + (i & 255)) = *(const float4*)(xsrc + i);
    __syncthreads();

    float lacc[8][4];
#pragma unroll
    for (int j = 0; j < 8; j++)
#pragma unroll
      for (int k = 0; k < 4; k++) lacc[j][k] = 0.f;

    for (int ks = 0; ks < 16; ks++) {
      const int k0 = kh + ks * 8;
      uint32_t a0 = F2U(xs[(mA + r) * XP + k0 + q]);
      uint32_t a1 = F2U(xs[(mA + r + 8) * XP + k0 + q]);
      uint32_t a2 = F2U(xs[(mA + r) * XP + k0 + q + 4]);
      uint32_t a3 = F2U(xs[(mA + r + 8) * XP + k0 + q + 4]);
#pragma unroll
      for (int nt = 0; nt < 8; nt++) {
        uint32_t b0 = F2U(ws[(nt * 8 + r) * WP + k0 + q]);
        uint32_t b1 = F2U(ws[(nt * 8 + r) * WP + k0 + q + 4]);
        mma_tf32(lacc[nt], a0, a1, a2, a3, b0, b1);
      }
    }
    if ((wid >> 2) == 0) {
#pragma unroll
      for (int nt = 0; nt < 8; nt++) {
        lg[(mA + r) * LP + nt * 8 + 2 * q] = lacc[nt][0];
        lg[(mA + r) * LP + nt * 8 + 2 * q + 1] = lacc[nt][1];
        lg[(mA + r + 8) * LP + nt * 8 + 2 * q] = lacc[nt][2];
        lg[(mA + r + 8) * LP + nt * 8 + 2 * q + 1] = lacc[nt][3];
      }
    }
    __syncthreads();
    if ((wid >> 2) == 1) {
#pragma unroll
      for (int nt = 0; nt < 8; nt++) {
        lg[(mA + r) * LP + nt * 8 + 2 * q] += lacc[nt][0];
        lg[(mA + r) * LP + nt * 8 + 2 * q + 1] += lacc[nt][1];
        lg[(mA + r + 8) * LP + nt * 8 + 2 * q] += lacc[nt][2];
        lg[(mA + r + 8) * LP + nt * 8 + 2 * q + 1] += lacc[nt][3];
      }
    }
    __syncthreads();

    {
      const int t = tid >> 2, qq = tid & 3;
      float v[16];
      float mx = -1e30f;
#pragma unroll
      for (int i = 0; i < 16; i++) {
        v[i] = lg[t * LP + qq * 16 + i] + sb[qq * 16 + i];
        mx = fmaxf(mx, v[i]);
      }
      mx = fmaxf(mx, __shfl_xor_sync(0xffffffffu, mx, 1));
      mx = fmaxf(mx, __shfl_xor_sync(0xffffffffu, mx, 2));
      float s = 0.f;
#pragma unroll
      for (int i = 0; i < 16; i++) {
        v[i] = __expf(v[i] - mx);
        s += v[i];
      }
      s += __shfl_xor_sync(0xffffffffu, s, 1);
      s += __shfl_xor_sync(0xffffffffu, s, 2);
      const float inv = 1.f / s;
      const size_t wrow =
          ((size_t)b * NN + tok0 + tile * 64 + t) * 64 + qq * 16;
#pragma unroll
      for (int i = 0; i < 16; i++) {
        float w = v[i] * inv;
        lg[t * LP + qq * 16 + i] = w;
        g_W[wrow + i] = w;
      }
    }
    __syncthreads();

    for (int ks = 0; ks < 8; ks++) {
      const int k0 = ks * 8;
      uint32_t a[2][4];
#pragma unroll
      for (int mt = 0; mt < 2; mt++) {
        const int h0 = hb + mt * 16;
        a[mt][0] = F2U(xs[(k0 + q) * XP + h0 + r]);
        a[mt][1] = F2U(xs[(k0 + q) * XP + h0 + r + 8]);
        a[mt][2] = F2U(xs[(k0 + q + 4) * XP + h0 + r]);
        a[mt][3] = F2U(xs[(k0 + q + 4) * XP + h0 + r + 8]);
      }
#pragma unroll
      for (int nt = 0; nt < 8; nt++) {
        uint32_t b0 = F2U(lg[(k0 + q) * LP + nt * 8 + r]);
        uint32_t b1 = F2U(lg[(k0 + q + 4) * LP + nt * 8 + r]);
        mma_tf32(stacc[0][nt], a[0][0], a[0][1], a[0][2], a[0][3], b0, b1);
        mma_tf32(stacc[1][nt], a[1][0], a[1][1], a[1][2], a[1][3], b0, b1);
      }
    }
  }

  float* pp = g_part + (size_t)(b * 128 + blockIdx.x) * 16384;
#pragma unroll
  for (int mt = 0; mt < 2; mt++) {
#pragma unroll
    for (int nt = 0; nt < 8; nt++) {
      const int h0 = hb + mt * 16 + r;
      const int s0 = nt * 8 + 2 * q;
      *(float2*)(pp + h0 * 64 + s0) =
          make_float2(stacc[mt][nt][0], stacc[mt][nt][1]);
      *(float2*)(pp + (h0 + 8) * 64 + s0) =
          make_float2(stacc[mt][nt][2], stacc[mt][nt][3]);
    }
  }
}

// ===========================================================================
// reduce pooling partials -> g_st
// ===========================================================================
__global__ __launch_bounds__(256) void k_reduce_st() {
  const int gt = blockIdx.x * 256 + threadIdx.x;
  const int bh = gt >> 14;
  const int pos = gt & 16383;
#pragma unroll
  for (int bi = 0; bi < 2; bi++) {
    const int bb = bh * 2 + bi;
    const float* p = g_part + (size_t)bb * 128 * 16384 + pos;
    float acc = 0.f;
#pragma unroll 4
    for (int j = 0; j < 128; j++) acc += p[(size_t)j * 16384];
    const int h = pos >> 6, s = pos & 63;
    g_st[bb * 16384 + s * 256 + h] = acc;
  }
}

// ===========================================================================
// Middle GEMM core: block = (colchunk of 32, batch). 256 threads.
// As (dyn smem) = batch activation rows [64][256]. thread = 1 col x 8 rows.
// ===========================================================================
__device__ __forceinline__ void stage64x256(float* As, const float* src,
                                            int tid) {
  for (int i = tid * 4; i < 16384; i += 1024)
    *(float4*)(As + i) = *(const float4*)(src + i);
}

__device__ __forceinline__ void fma64(const float* __restrict__ As,
                                      const float* __restrict__ wp,
                                      float acc[8], int r0, int k0) {
  float4 wv[16];
#pragma unroll
  for (int j = 0; j < 16; j++) wv[j] = *(const float4*)(wp + j * 4);
#pragma unroll
  for (int j = 0; j < 16; j++) {
#pragma unroll
    for (int r = 0; r < 8; r++) {
      float4 s = *(const float4*)(As + (r0 + r) * 256 + k0 + j * 4);
      acc[r] += s.x * wv[j].x + s.y * wv[j].y + s.z * wv[j].z + s.w * wv[j].w;
    }
  }
}

// gate: st_gated = st + sigmoid(st @ gw^T + gb) * estate
__global__ __launch_bounds__(256) void k_gate(
    const float* __restrict__ gw, const float* __restrict__ gb,
    const float* __restrict__ estate) {
  extern __shared__ float As[];
  const int tid = threadIdx.x;
  const int b = blockIdx.y;
  stage64x256(As, g_st + b * 16384, tid);
  const int col = blockIdx.x * 32 + (tid & 31);
  const int r0 = (tid >> 5) * 8;
  const float* wr = gw + col * 256;
  float acc[8];
#pragma unroll
  for (int r = 0; r < 8; r++) acc[r] = gb[col];
  __syncthreads();
#pragma unroll
  for (int kc = 0; kc < 4; kc++) fma64(As, wr + kc * 64, acc, r0, kc * 64);
#pragma unroll
  for (int r = 0; r < 8; r++) {
    const int s = r0 + r;
    float gate = 1.f / (1.f + expf(-acc[r]));
    g_stg[b * 16384 + s * 256 + col] = As[s * 256 + col] + gate * estate[s * 256 + col];
  }
}

// qkv: [768] outputs per row
__global__ __launch_bounds__(256) void k_qkv(
    const float* __restrict__ in_w, const float* __restrict__ in_b) {
  extern __shared__ float As[];
  const int tid = threadIdx.x;
  const int b = blockIdx.y;
  stage64x256(As, g_stg + b * 16384, tid);
  const int col = blockIdx.x * 32 + (tid & 31);
  const int r0 = (tid >> 5) * 8;
  const float* wr = in_w + col * 256;
  float acc[8];
#pragma unroll
  for (int r = 0; r < 8; r++) acc[r] = in_b[col];
  __syncthreads();
#pragma unroll
  for (int kc = 0; kc < 4; kc++) fma64(As, wr + kc * 64, acc, r0, kc * 64);
#pragma unroll
  for (int r = 0; r < 8; r++)
    g_qkv[(b * 64 + r0 + r) * 768 + col] = acc[r];
}

// attention per (b, head): 32 blocks
__global__ __launch_bounds__(256) void k_attn() {
  int b = blockIdx.x >> 3, hh = blockIdx.x & 7;
  __shared__ float q[64][32], kk[64][33], vv[64][32], p[64][65];
  int tid = threadIdx.x;
  for (int i = tid; i < 2048; i += 256) {
    int s = i >> 5, d = i & 31;
    int base = (b * 64 + s) * 768 + hh * 32 + d;
    q[s][d] = g_qkv[base];
    kk[s][d] = g_qkv[base + 256];
    vv[s][d] = g_qkv[base + 512];
  }
  __syncthreads();
  for (int idx = tid; idx < 4096; idx += 256) {
    int qi = idx >> 6, ki = idx & 63;
    float a = 0.f;
#pragma unroll
    for (int d = 0; d < 32; d++) a += q[qi][d] * kk[ki][d];
    p[qi][ki] = a * 0.17677669529663687f;
  }
  __syncthreads();
  {
    const int row = tid >> 2, qq = tid & 3;
    float v[16], mx = -1e30f;
#pragma unroll
    for (int i = 0; i < 16; i++) {
      v[i] = p[row][qq * 16 + i];
      mx = fmaxf(mx, v[i]);
    }
    mx = fmaxf(mx, __shfl_xor_sync(0xffffffffu, mx, 1));
    mx = fmaxf(mx, __shfl_xor_sync(0xffffffffu, mx, 2));
    float s = 0.f;
#pragma unroll
    for (int i = 0; i < 16; i++) { v[i] = __expf(v[i] - mx); s += v[i]; }
    s += __shfl_xor_sync(0xffffffffu, s, 1);
    s += __shfl_xor_sync(0xffffffffu, s, 2);
    const float inv = 1.f / s;
#pragma unroll
    for (int i = 0; i < 16; i++) p[row][qq * 16 + i] = v[i] * inv;
  }
  __syncthreads();
  for (int idx = tid; idx < 2048; idx += 256) {
    int qi = idx >> 5, d = idx & 31;
    float a = 0.f;
#pragma unroll
    for (int j = 0; j < 64; j++) a += p[qi][j] * vv[j][d];
    g_ao[(b * 64 + qi) * 256 + hh * 32 + d] = a;
  }
}

// attn output projection (pre-residual, pre-LN)
__global__ __launch_bounds__(256) void k_proj(
    const float* __restrict__ out_w, const float* __restrict__ out_b) {
  extern __shared__ float As[];
  const int tid = threadIdx.x;
  const int b = blockIdx.y;
  stage64x256(As, g_ao + b * 16384, tid);
  const int col = blockIdx.x * 32 + (tid & 31);
  const int r0 = (tid >> 5) * 8;
  const float* wr = out_w + col * 256;
  float acc[8];
#pragma unroll
  for (int r = 0; r < 8; r++) acc[r] = out_b[col];
  __syncthreads();
#pragma unroll
  for (int kc = 0; kc < 4; kc++) fma64(As, wr + kc * 64, acc, r0, kc * 64);
#pragma unroll
  for (int r = 0; r < 8; r++)
    g_pro[(b * 64 + r0 + r) * 256 + col] = acc[r];
}

// generic LN: out = LN(a + p0 [+ p1])
__device__ __forceinline__ void ln4_reduce(float yv[4], float mu[4], float var[4],
                                           float wsum[4][8], float wsq[4][8],
                                           int tid) {
  float s1[4], s2[4];
#pragma unroll
  for (int r = 0; r < 4; r++) { s1[r] = yv[r]; s2[r] = yv[r] * yv[r]; }
#pragma unroll
  for (int off = 16; off; off >>= 1)
#pragma unroll
    for (int r = 0; r < 4; r++) {
      s1[r] += __shfl_xor_sync(0xffffffffu, s1[r], off);
      s2[r] += __shfl_xor_sync(0xffffffffu, s2[r], off);
    }
  int w = tid >> 5, lane = tid & 31;
  if (lane == 0)
#pragma unroll
    for (int r = 0; r < 4; r++) { wsum[r][w] = s1[r]; wsq[r][w] = s2[r]; }
  __syncthreads();
#pragma unroll
  for (int r = 0; r < 4; r++) {
    float a = 0.f, bq = 0.f;
#pragma unroll
    for (int ww = 0; ww < 8; ww++) { a += wsum[r][ww]; bq += wsq[r][ww]; }
    mu[r] = a * (1.f / 256.f);
    var[r] = bq * (1.f / 256.f) - mu[r] * mu[r];
  }
}

__global__ __launch_bounds__(256) void k_ln(
    const float* __restrict__ a, const float* __restrict__ p0,
    const float* __restrict__ p1, int use2, const float* __restrict__ g,
    const float* __restrict__ bb, float* __restrict__ out) {
  int bs0 = blockIdx.x * 4;
  __shared__ float wsum[4][8], wsq[4][8];
  int tid = threadIdx.x;
  float yv[4];
#pragma unroll
  for (int r = 0; r < 4; r++) {
    int idx = (bs0 + r) * 256 + tid;
    yv[r] = a[idx] + p0[idx];
    if (use2) yv[r] += p1[idx];
  }
  float mu[4], var[4];
  ln4_reduce(yv, mu, var, wsum, wsq, tid);
#pragma unroll
  for (int r = 0; r < 4; r++)
    out[(bs0 + r) * 256 + tid] =
        (yv[r] - mu[r]) * rsqrtf(var[r] + 1e-5f) * g[tid] + bb[tid];
}

// ffn1: [1024] outputs, GELU
__global__ __launch_bounds__(256) void k_ffn1(
    const float* __restrict__ f1_w, const float* __restrict__ f1_b) {
  extern __shared__ float As[];
  const int tid = threadIdx.x;
  const int b = blockIdx.y;
  stage64x256(As, g_st1 + b * 16384, tid);
  const int col = blockIdx.x * 32 + (tid & 31);
  const int r0 = (tid >> 5) * 8;
  const float* wr = f1_w + col * 256;
  float acc[8];
#pragma unroll
  for (int r = 0; r < 8; r++) acc[r] = f1_b[col];
  __syncthreads();
#pragma unroll
  for (int kc = 0; kc < 4; kc++) fma64(As, wr + kc * 64, acc, r0, kc * 64);
#pragma unroll
  for (int r = 0; r < 8; r++) {
    float v = acc[r];
    g_h[(b * 64 + r0 + r) * 1024 + col] =
        0.5f * v * (1.f + erff(v * 0.7071067811865475f));
  }
}

// ffn2: K=1024 with 2-way k-split (blockIdx.z), partials to g_f2p
__global__ __launch_bounds__(256) void k_ffn2(
    const float* __restrict__ f2_w, const float* __restrict__ f2_b) {
  extern __shared__ float As[];
  const int tid = threadIdx.x;
  const int b = blockIdx.y;
  const int z = blockIdx.z;
  const int col = blockIdx.x * 32 + (tid & 31);
  const int r0 = (tid >> 5) * 8;
  const float* wr = f2_w + col * 1024 + z * 512;
  float acc[8];
#pragma unroll
  for (int r = 0; r < 8; r++) acc[r] = (z == 0) ? f2_b[col] : 0.f;

  for (int c = 0; c < 2; c++) {
    __syncthreads();
    // stage h rows k-range [z*512 + c*256, +256)
    for (int i = tid * 4; i < 16384; i += 1024) {
      int row = i >> 8, kl = i & 255;
      *(float4*)(As + i) =
          *(const float4*)(g_h + (b * 64 + row) * 1024 + z * 512 + c * 256 + kl);
    }
    __syncthreads();
#pragma unroll
    for (int kc = 0; kc < 4; kc++)
      fma64(As, wr + c * 256 + kc * 64, acc, r0, kc * 64);
  }
#pragma unroll
  for (int r = 0; r < 8; r++)
    g_f2p[z][(b * 64 + r0 + r) * 256 + col] = acc[r];
}

// ===========================================================================
// KC: decode out = W @ st2 + x via tf32 mma (unchanged from R4)
// ===========================================================================
__global__ __launch_bounds__(256) void k_decode(const float* __restrict__ x,
                                                float* __restrict__ out) {
  extern __shared__ float sm[];
  float* st2s = sm;              // [64][SP]
  float* Ws = sm + 64 * SP;      // [128][AP]
  const int tid = threadIdx.x;
  const int b = blockIdx.y;
  const int n0 = blockIdx.x * 128;

  for (int i = tid * 4; i < 16384; i += 1024)
    *(float4*)(st2s + (i >> 8) * SP + (i & 255)) =
        *(const float4*)(g_st2 + b * 16384 + i);
  for (int i = tid * 4; i < 8192; i += 1024)
    *(float4*)(Ws + (i >> 6) * AP + (i & 63)) =
        *(const float4*)(g_W + ((size_t)b * NN + n0 + (i >> 6)) * 64 + (i & 63));
  __syncthreads();

  const int wid = tid >> 5, lane = tid & 31;
  const int r = lane >> 2, q = lane & 3;
  const int m0 = wid * 16;

  for (int nh = 0; nh < 2; nh++) {
    float acc[16][4];
#pragma unroll
    for (int i = 0; i < 16; i++)
#pragma unroll
      for (int j = 0; j < 4; j++) acc[i][j] = 0.f;

    for (int ks = 0; ks < 8; ks++) {
      const int k0 = ks * 8;
      uint32_t a0 = F2U(Ws[(m0 + r) * AP + k0 + q]);
      uint32_t a1 = F2U(Ws[(m0 + r + 8) * AP + k0 + q]);
      uint32_t a2 = F2U(Ws[(m0 + r) * AP + k0 + q + 4]);
      uint32_t a3 = F2U(Ws[(m0 + r + 8) * AP + k0 + q + 4]);
#pragma unroll
      for (int nt = 0; nt < 16; nt++) {
        const int n = nh * 128 + nt * 8;
        uint32_t b0 = F2U(st2s[(k0 + q) * SP + n + r]);
        uint32_t b1 = F2U(st2s[(k0 + q + 4) * SP + n + r]);
        mma_tf32(acc[nt], a0, a1, a2, a3, b0, b1);
      }
    }
#pragma unroll
    for (int nt = 0; nt < 16; nt++) {
      const int n = nh * 128 + nt * 8 + 2 * q;
      const size_t base0 = ((size_t)b * NN + n0 + m0 + r) * 256 + n;
      const size_t base1 = base0 + 8 * 256;
      float2 xv0 = *(const float2*)(x + base0);
      float2 xv1 = *(const float2*)(x + base1);
      *(float2*)(out + base0) = make_float2(acc[nt][0] + xv0.x, acc[nt][1] + xv0.y);
      *(float2*)(out + base1) = make_float2(acc[nt][2] + xv1.x, acc[nt][3] + xv1.y);
    }
  }
}

// ===========================================================================
extern "C" void kernel_launch(void* const* d_in, const int* in_sizes, int n_in,
                              void* d_out, int out_size) {
  const float* x = (const float*)d_in[0];
  const float* sq_w = (const float*)d_in[1];
  const float* sq_b = (const float*)d_in[2];
  const float* eid_state = (const float*)d_in[3];
  const float* eid_gw = (const float*)d_in[4];
  const float* eid_gb = (const float*)d_in[5];
  const float* in_w = (const float*)d_in[6];
  const float* in_b = (const float*)d_in[7];
  const float* out_w = (const float*)d_in[8];
  const float* out_b = (const float*)d_in[9];
  const float* n1_g = (const float*)d_in[10];
  const float* n1_b = (const float*)d_in[11];
  const float* n2_g = (const float*)d_in[12];
  const float* n2_b = (const float*)d_in[13];
  const float* f1_w = (const float*)d_in[14];
  const float* f1_b = (const float*)d_in[15];
  const float* f2_w = (const float*)d_in[16];
  const float* f2_b = (const float*)d_in[17];
  float* out = (float*)d_out;

  const int smem_ka = (64 * XP + 64 * WP + 64 * LP + 64) * 4;
  const int smem_kc = (64 * SP + 128 * AP) * 4;
  const int smem_mid = 64 * 256 * 4;  // 64KB
  cudaFuncSetAttribute(k_assign_pool, cudaFuncAttributeMaxDynamicSharedMemorySize, smem_ka);
  cudaFuncSetAttribute(k_decode, cudaFuncAttributeMaxDynamicSharedMemorySize, smem_kc);
  cudaFuncSetAttribute(k_gate, cudaFuncAttributeMaxDynamicSharedMemorySize, smem_mid);
  cudaFuncSetAttribute(k_qkv, cudaFuncAttributeMaxDynamicSharedMemorySize, smem_mid);
  cudaFuncSetAttribute(k_proj, cudaFuncAttributeMaxDynamicSharedMemorySize, smem_mid);
  cudaFuncSetAttribute(k_ffn1, cudaFuncAttributeMaxDynamicSharedMemorySize, smem_mid);
  cudaFuncSetAttribute(k_ffn2, cudaFuncAttributeMaxDynamicSharedMemorySize, smem_mid);

  float *p_stg, *p_pro, *p_st1, *p_f2p0, *p_f2p1, *p_st2;
  cudaGetSymbolAddress((void**)&p_stg, g_stg);
  cudaGetSymbolAddress((void**)&p_pro, g_pro);
  cudaGetSymbolAddress((void**)&p_st1, g_st1);
  cudaGetSymbolAddress((void**)&p_f2p0, g_f2p);
  p_f2p1 = p_f2p0 + BB * SS * HH;
  cudaGetSymbolAddress((void**)&p_st2, g_st2);

  k_assign_pool<<<dim3(128, BB), 256, smem_ka>>>(x, sq_w, sq_b);
  k_reduce_st<<<128, 256>>>();
  k_gate<<<dim3(8, BB), 256, smem_mid>>>(eid_gw, eid_gb, eid_state);
  k_qkv<<<dim3(24, BB), 256, smem_mid>>>(in_w, in_b);
  k_attn<<<32, 256>>>();
  k_proj<<<dim3(8, BB), 256, smem_mid>>>(out_w, out_b);
  k_ln<<<64, 256>>>(p_stg, p_pro, p_pro, 0, n1_g, n1_b, p_st1);
  k_ffn1<<<dim3(32, BB), 256, smem_mid>>>(f1_w, f1_b);
  k_ffn2<<<dim3(8, BB, 2), 256, smem_mid>>>(f2_w, f2_b);
  k_ln<<<64, 256>>>(p_st1, p_f2p0, p_f2p1, 1, n2_g, n2_b, p_st2);
  k_decode<<<dim3(256, BB), 256, smem_kc>>>(x, out);
}

// round 7
// speedup vs baseline: 1.8723x; 1.1325x over previous
#include <cuda_runtime.h>
#include <stdint.h>
#include <math.h>

#define BB 4
#define NN 32768
#define HH 256
#define SS 64

#define XP 268   // xs row pad (floats)
#define WP 268   // sq_w row pad
#define LP 72    // logits/W tile row pad
#define SP 268   // st2 row pad (KC)
#define AP 68    // W tile row pad (KC)

// ---------------- scratch (static device allocations only) ----------------
__device__ float g_W[(size_t)BB * NN * SS];          // 32 MB soft-assignment weights
__device__ float g_part[(size_t)512 * 16384];        // 33.5MB pooling partials
__device__ float g_st[BB * SS * HH];
__device__ float g_stg[BB * SS * HH];                // gated st
__device__ float g_qkv[BB * SS * 3 * HH];
__device__ float g_ao[BB * SS * HH];
__device__ float g_pro[BB * SS * HH];                // attn out-proj (pre-LN)
__device__ float g_st1[BB * SS * HH];
__device__ float g_h[BB * SS * 4 * HH];
__device__ float g_f2p[4][BB * SS * HH];             // ffn2 k-split partials
__device__ float g_st2[BB * SS * HH];

// ---- m16n8k8 tf32 mma helper --------------------------------------------
__device__ __forceinline__ void mma_tf32(float c[4], uint32_t a0, uint32_t a1,
                                         uint32_t a2, uint32_t a3, uint32_t b0,
                                         uint32_t b1) {
  asm volatile(
      "mma.sync.aligned.m16n8k8.row.col.f32.tf32.tf32.f32 "
      "{%0,%1,%2,%3}, {%4,%5,%6,%7}, {%8,%9}, {%0,%1,%2,%3};\n"
      : "+f"(c[0]), "+f"(c[1]), "+f"(c[2]), "+f"(c[3])
      : "r"(a0), "r"(a1), "r"(a2), "r"(a3), "r"(b0), "r"(b1));
}
#define F2U __float_as_uint

// ===========================================================================
// KA: fused logits(tf32 mma) + softmax + pooling (unchanged)
// ===========================================================================
__global__ __launch_bounds__(256) void k_assign_pool(
    const float* __restrict__ x, const float* __restrict__ sq_w,
    const float* __restrict__ sq_b) {
  extern __shared__ float sm[];
  float* xs = sm;                 // [64][XP]
  float* ws = sm + 64 * XP;       // [64][WP]
  float* lg = ws + 64 * WP;       // [64][LP]
  float* sb = lg + 64 * LP;       // [64]

  const int tid = threadIdx.x;
  const int b = blockIdx.y;
  const size_t tok0 = (size_t)blockIdx.x * 256;
  const float* xb = x + (size_t)b * NN * HH;

  for (int i = tid * 4; i < 64 * 256; i += 1024) {
    float4 v = *(const float4*)(sq_w + i);
    *(float4*)(ws + (i >> 8) * WP + (i & 255)) = v;
  }
  if (tid < 64) sb[tid] = sq_b[tid];

  const int wid = tid >> 5, lane = tid & 31;
  const int r = lane >> 2, q = lane & 3;
  const int mA = (wid & 3) * 16;
  const int kh = (wid >> 2) * 128;
  const int hb = wid * 32;

  float stacc[2][8][4];
#pragma unroll
  for (int i = 0; i < 2; i++)
#pragma unroll
    for (int j = 0; j < 8; j++)
#pragma unroll
      for (int k = 0; k < 4; k++) stacc[i][j][k] = 0.f;

  for (int tile = 0; tile < 4; tile++) {
    __syncthreads();
    const float* xsrc = xb + (tok0 + tile * 64) * 256;
    for (int i = tid * 4; i < 16384; i += 1024)
      *(float4*)(xs + (i >> 8) * XP + (i & 255)) = *(const float4*)(xsrc + i);
    __syncthreads();

    float lacc[8][4];
#pragma unroll
    for (int j = 0; j < 8; j++)
#pragma unroll
      for (int k = 0; k < 4; k++) lacc[j][k] = 0.f;

    for (int ks = 0; ks < 16; ks++) {
      const int k0 = kh + ks * 8;
      uint32_t a0 = F2U(xs[(mA + r) * XP + k0 + q]);
      uint32_t a1 = F2U(xs[(mA + r + 8) * XP + k0 + q]);
      uint32_t a2 = F2U(xs[(mA + r) * XP + k0 + q + 4]);
      uint32_t a3 = F2U(xs[(mA + r + 8) * XP + k0 + q + 4]);
#pragma unroll
      for (int nt = 0; nt < 8; nt++) {
        uint32_t b0 = F2U(ws[(nt * 8 + r) * WP + k0 + q]);
        uint32_t b1 = F2U(ws[(nt * 8 + r) * WP + k0 + q + 4]);
        mma_tf32(lacc[nt], a0, a1, a2, a3, b0, b1);
      }
    }
    if ((wid >> 2) == 0) {
#pragma unroll
      for (int nt = 0; nt < 8; nt++) {
        lg[(mA + r) * LP + nt * 8 + 2 * q] = lacc[nt][0];
        lg[(mA + r) * LP + nt * 8 + 2 * q + 1] = lacc[nt][1];
        lg[(mA + r + 8) * LP + nt * 8 + 2 * q] = lacc[nt][2];
        lg[(mA + r + 8) * LP + nt * 8 + 2 * q + 1] = lacc[nt][3];
      }
    }
    __syncthreads();
    if ((wid >> 2) == 1) {
#pragma unroll
      for (int nt = 0; nt < 8; nt++) {
        lg[(mA + r) * LP + nt * 8 + 2 * q] += lacc[nt][0];
        lg[(mA + r) * LP + nt * 8 + 2 * q + 1] += lacc[nt][1];
        lg[(mA + r + 8) * LP + nt * 8 + 2 * q] += lacc[nt][2];
        lg[(mA + r + 8) * LP + nt * 8 + 2 * q + 1] += lacc[nt][3];
      }
    }
    __syncthreads();

    {
      const int t = tid >> 2, qq = tid & 3;
      float v[16];
      float mx = -1e30f;
#pragma unroll
      for (int i = 0; i < 16; i++) {
        v[i] = lg[t * LP + qq * 16 + i] + sb[qq * 16 + i];
        mx = fmaxf(mx, v[i]);
      }
      mx = fmaxf(mx, __shfl_xor_sync(0xffffffffu, mx, 1));
      mx = fmaxf(mx, __shfl_xor_sync(0xffffffffu, mx, 2));
      float s = 0.f;
#pragma unroll
      for (int i = 0; i < 16; i++) {
        v[i] = __expf(v[i] - mx);
        s += v[i];
      }
      s += __shfl_xor_sync(0xffffffffu, s, 1);
      s += __shfl_xor_sync(0xffffffffu, s, 2);
      const float inv = 1.f / s;
      const size_t wrow =
          ((size_t)b * NN + tok0 + tile * 64 + t) * 64 + qq * 16;
#pragma unroll
      for (int i = 0; i < 16; i++) {
        float w = v[i] * inv;
        lg[t * LP + qq * 16 + i] = w;
        g_W[wrow + i] = w;
      }
    }
    __syncthreads();

    for (int ks = 0; ks < 8; ks++) {
      const int k0 = ks * 8;
      uint32_t a[2][4];
#pragma unroll
      for (int mt = 0; mt < 2; mt++) {
        const int h0 = hb + mt * 16;
        a[mt][0] = F2U(xs[(k0 + q) * XP + h0 + r]);
        a[mt][1] = F2U(xs[(k0 + q) * XP + h0 + r + 8]);
        a[mt][2] = F2U(xs[(k0 + q + 4) * XP + h0 + r]);
        a[mt][3] = F2U(xs[(k0 + q + 4) * XP + h0 + r + 8]);
      }
#pragma unroll
      for (int nt = 0; nt < 8; nt++) {
        uint32_t b0 = F2U(lg[(k0 + q) * LP + nt * 8 + r]);
        uint32_t b1 = F2U(lg[(k0 + q + 4) * LP + nt * 8 + r]);
        mma_tf32(stacc[0][nt], a[0][0], a[0][1], a[0][2], a[0][3], b0, b1);
        mma_tf32(stacc[1][nt], a[1][0], a[1][1], a[1][2], a[1][3], b0, b1);
      }
    }
  }

  float* pp = g_part + (size_t)(b * 128 + blockIdx.x) * 16384;
#pragma unroll
  for (int mt = 0; mt < 2; mt++) {
#pragma unroll
    for (int nt = 0; nt < 8; nt++) {
      const int h0 = hb + mt * 16 + r;
      const int s0 = nt * 8 + 2 * q;
      *(float2*)(pp + h0 * 64 + s0) =
          make_float2(stacc[mt][nt][0], stacc[mt][nt][1]);
      *(float2*)(pp + (h0 + 8) * 64 + s0) =
          make_float2(stacc[mt][nt][2], stacc[mt][nt][3]);
    }
  }
}

// ===========================================================================
// reduce pooling partials -> g_st  (float4 loads, MLP 8)
// ===========================================================================
__global__ __launch_bounds__(256) void k_reduce_st() {
  const int gt = blockIdx.x * 256 + threadIdx.x;  // 0..16383
  const int bb = gt >> 12;
  const int p4 = (gt & 4095) * 4;
  const float* p = g_part + (size_t)bb * 128 * 16384 + p4;
  float4 acc = make_float4(0.f, 0.f, 0.f, 0.f);
#pragma unroll 8
  for (int j = 0; j < 128; j++) {
    float4 v = *(const float4*)(p + (size_t)j * 16384);
    acc.x += v.x; acc.y += v.y; acc.z += v.z; acc.w += v.w;
  }
  const int h = p4 >> 6, s0 = p4 & 63;
  float* dst = g_st + bb * 16384 + h;
  dst[(s0 + 0) * 256] = acc.x;
  dst[(s0 + 1) * 256] = acc.y;
  dst[(s0 + 2) * 256] = acc.z;
  dst[(s0 + 3) * 256] = acc.w;
}

// ===========================================================================
// Middle GEMM core. smem: As[64][256] + wsT[256][33].
// Weights staged coalesced & transposed; inner loop conflict-free.
// ===========================================================================
__device__ __forceinline__ void stage64x256(float* As, const float* src,
                                            int tid) {
  for (int i = tid * 4; i < 16384; i += 1024)
    *(float4*)(As + i) = *(const float4*)(src + i);
}

__device__ __forceinline__ void stage_wsT(float* wsT, const float* w, int ldw,
                                          int c0, int koff, int tid) {
  for (int i = tid * 4; i < 32 * 256; i += 1024) {
    int cl = i >> 8, k = i & 255;
    float4 v = *(const float4*)(w + (size_t)(c0 + cl) * ldw + koff + k);
    wsT[(k + 0) * 33 + cl] = v.x;
    wsT[(k + 1) * 33 + cl] = v.y;
    wsT[(k + 2) * 33 + cl] = v.z;
    wsT[(k + 3) * 33 + cl] = v.w;
  }
}

__device__ __forceinline__ void mid_core(const float* __restrict__ As,
                                         const float* __restrict__ wsT,
                                         float acc[8], int col, int r0) {
#pragma unroll 8
  for (int k = 0; k < 256; k += 4) {
    float w0 = wsT[(k + 0) * 33 + col];
    float w1 = wsT[(k + 1) * 33 + col];
    float w2 = wsT[(k + 2) * 33 + col];
    float w3 = wsT[(k + 3) * 33 + col];
#pragma unroll
    for (int r = 0; r < 8; r++) {
      float4 a = *(const float4*)(As + (r0 + r) * 256 + k);
      acc[r] += a.x * w0 + a.y * w1 + a.z * w2 + a.w * w3;
    }
  }
}

#define MID_SMEM ((64 * 256 + 256 * 33) * 4)

// gate: st_gated = st + sigmoid(st @ gw^T + gb) * estate
__global__ __launch_bounds__(256) void k_gate(
    const float* __restrict__ gw, const float* __restrict__ gb,
    const float* __restrict__ estate) {
  extern __shared__ float smm[];
  float* As = smm;
  float* wsT = smm + 64 * 256;
  const int tid = threadIdx.x;
  const int b = blockIdx.y;
  const int c0 = blockIdx.x * 32;
  stage64x256(As, g_st + b * 16384, tid);
  stage_wsT(wsT, gw, 256, c0, 0, tid);
  const int col = tid & 31;
  const int r0 = (tid >> 5) * 8;
  float acc[8];
#pragma unroll
  for (int r = 0; r < 8; r++) acc[r] = gb[c0 + col];
  __syncthreads();
  mid_core(As, wsT, acc, col, r0);
#pragma unroll
  for (int r = 0; r < 8; r++) {
    const int s = r0 + r;
    float gate = 1.f / (1.f + expf(-acc[r]));
    g_stg[b * 16384 + s * 256 + c0 + col] =
        As[s * 256 + c0 + col] + gate * estate[s * 256 + c0 + col];
  }
}

__global__ __launch_bounds__(256) void k_qkv(
    const float* __restrict__ in_w, const float* __restrict__ in_b) {
  extern __shared__ float smm[];
  float* As = smm;
  float* wsT = smm + 64 * 256;
  const int tid = threadIdx.x;
  const int b = blockIdx.y;
  const int c0 = blockIdx.x * 32;
  stage64x256(As, g_stg + b * 16384, tid);
  stage_wsT(wsT, in_w, 256, c0, 0, tid);
  const int col = tid & 31;
  const int r0 = (tid >> 5) * 8;
  float acc[8];
#pragma unroll
  for (int r = 0; r < 8; r++) acc[r] = in_b[c0 + col];
  __syncthreads();
  mid_core(As, wsT, acc, col, r0);
#pragma unroll
  for (int r = 0; r < 8; r++)
    g_qkv[(b * 64 + r0 + r) * 768 + c0 + col] = acc[r];
}

// attention per (b, head): 32 blocks
__global__ __launch_bounds__(256) void k_attn() {
  int b = blockIdx.x >> 3, hh = blockIdx.x & 7;
  __shared__ float q[64][32], kk[64][33], vv[64][32], p[64][65];
  int tid = threadIdx.x;
  for (int i = tid; i < 2048; i += 256) {
    int s = i >> 5, d = i & 31;
    int base = (b * 64 + s) * 768 + hh * 32 + d;
    q[s][d] = g_qkv[base];
    kk[s][d] = g_qkv[base + 256];
    vv[s][d] = g_qkv[base + 512];
  }
  __syncthreads();
  for (int idx = tid; idx < 4096; idx += 256) {
    int qi = idx >> 6, ki = idx & 63;
    float a = 0.f;
#pragma unroll
    for (int d = 0; d < 32; d++) a += q[qi][d] * kk[ki][d];
    p[qi][ki] = a * 0.17677669529663687f;
  }
  __syncthreads();
  {
    const int row = tid >> 2, qq = tid & 3;
    float v[16], mx = -1e30f;
#pragma unroll
    for (int i = 0; i < 16; i++) {
      v[i] = p[row][qq * 16 + i];
      mx = fmaxf(mx, v[i]);
    }
    mx = fmaxf(mx, __shfl_xor_sync(0xffffffffu, mx, 1));
    mx = fmaxf(mx, __shfl_xor_sync(0xffffffffu, mx, 2));
    float s = 0.f;
#pragma unroll
    for (int i = 0; i < 16; i++) { v[i] = __expf(v[i] - mx); s += v[i]; }
    s += __shfl_xor_sync(0xffffffffu, s, 1);
    s += __shfl_xor_sync(0xffffffffu, s, 2);
    const float inv = 1.f / s;
#pragma unroll
    for (int i = 0; i < 16; i++) p[row][qq * 16 + i] = v[i] * inv;
  }
  __syncthreads();
  // AV: thread = (d, 8 rows of qi)
  {
    const int d = tid & 31;
    const int q0 = (tid >> 5) * 8;
    float acc[8];
#pragma unroll
    for (int r = 0; r < 8; r++) acc[r] = 0.f;
    for (int j = 0; j < 64; j++) {
      float vvj = vv[j][d];
#pragma unroll
      for (int r = 0; r < 8; r++) acc[r] += p[q0 + r][j] * vvj;
    }
#pragma unroll
    for (int r = 0; r < 8; r++)
      g_ao[(b * 64 + q0 + r) * 256 + hh * 32 + d] = acc[r];
  }
}

__global__ __launch_bounds__(256) void k_proj(
    const float* __restrict__ out_w, const float* __restrict__ out_b) {
  extern __shared__ float smm[];
  float* As = smm;
  float* wsT = smm + 64 * 256;
  const int tid = threadIdx.x;
  const int b = blockIdx.y;
  const int c0 = blockIdx.x * 32;
  stage64x256(As, g_ao + b * 16384, tid);
  stage_wsT(wsT, out_w, 256, c0, 0, tid);
  const int col = tid & 31;
  const int r0 = (tid >> 5) * 8;
  float acc[8];
#pragma unroll
  for (int r = 0; r < 8; r++) acc[r] = out_b[c0 + col];
  __syncthreads();
  mid_core(As, wsT, acc, col, r0);
#pragma unroll
  for (int r = 0; r < 8; r++)
    g_pro[(b * 64 + r0 + r) * 256 + c0 + col] = acc[r];
}

// LN: out = LN(a + sum of np partials)
__device__ __forceinline__ void ln4_reduce(float yv[4], float mu[4], float var[4],
                                           float wsum[4][8], float wsq[4][8],
                                           int tid) {
  float s1[4], s2[4];
#pragma unroll
  for (int r = 0; r < 4; r++) { s1[r] = yv[r]; s2[r] = yv[r] * yv[r]; }
#pragma unroll
  for (int off = 16; off; off >>= 1)
#pragma unroll
    for (int r = 0; r < 4; r++) {
      s1[r] += __shfl_xor_sync(0xffffffffu, s1[r], off);
      s2[r] += __shfl_xor_sync(0xffffffffu, s2[r], off);
    }
  int w = tid >> 5, lane = tid & 31;
  if (lane == 0)
#pragma unroll
    for (int r = 0; r < 4; r++) { wsum[r][w] = s1[r]; wsq[r][w] = s2[r]; }
  __syncthreads();
#pragma unroll
  for (int r = 0; r < 4; r++) {
    float a = 0.f, bq = 0.f;
#pragma unroll
    for (int ww = 0; ww < 8; ww++) { a += wsum[r][ww]; bq += wsq[r][ww]; }
    mu[r] = a * (1.f / 256.f);
    var[r] = bq * (1.f / 256.f) - mu[r] * mu[r];
  }
}

__global__ __launch_bounds__(256) void k_ln(
    const float* __restrict__ a, const float* __restrict__ parts, int np,
    const float* __restrict__ g, const float* __restrict__ bb,
    float* __restrict__ out) {
  int bs0 = blockIdx.x * 4;
  __shared__ float wsum[4][8], wsq[4][8];
  int tid = threadIdx.x;
  float yv[4];
#pragma unroll
  for (int r = 0; r < 4; r++) {
    int idx = (bs0 + r) * 256 + tid;
    float v = a[idx];
    for (int pz = 0; pz < np; pz++) v += parts[pz * (BB * SS * HH) + idx];
    yv[r] = v;
  }
  float mu[4], var[4];
  ln4_reduce(yv, mu, var, wsum, wsq, tid);
#pragma unroll
  for (int r = 0; r < 4; r++)
    out[(bs0 + r) * 256 + tid] =
        (yv[r] - mu[r]) * rsqrtf(var[r] + 1e-5f) * g[tid] + bb[tid];
}

// ffn1: 1024 outputs, GELU
__global__ __launch_bounds__(256) void k_ffn1(
    const float* __restrict__ f1_w, const float* __restrict__ f1_b) {
  extern __shared__ float smm[];
  float* As = smm;
  float* wsT = smm + 64 * 256;
  const int tid = threadIdx.x;
  const int b = blockIdx.y;
  const int c0 = blockIdx.x * 32;
  stage64x256(As, g_st1 + b * 16384, tid);
  stage_wsT(wsT, f1_w, 256, c0, 0, tid);
  const int col = tid & 31;
  const int r0 = (tid >> 5) * 8;
  float acc[8];
#pragma unroll
  for (int r = 0; r < 8; r++) acc[r] = f1_b[c0 + col];
  __syncthreads();
  mid_core(As, wsT, acc, col, r0);
#pragma unroll
  for (int r = 0; r < 8; r++) {
    float v = acc[r];
    g_h[(b * 64 + r0 + r) * 1024 + c0 + col] =
        0.5f * v * (1.f + erff(v * 0.7071067811865475f));
  }
}

// ffn2: K=1024 with 4-way k-split (blockIdx.z)
__global__ __launch_bounds__(256) void k_ffn2(
    const float* __restrict__ f2_w, const float* __restrict__ f2_b) {
  extern __shared__ float smm[];
  float* As = smm;
  float* wsT = smm + 64 * 256;
  const int tid = threadIdx.x;
  const int b = blockIdx.y;
  const int z = blockIdx.z;
  const int c0 = blockIdx.x * 32;
  // stage h slice [64][256] for k-range z*256..+256
  for (int i = tid * 4; i < 16384; i += 1024) {
    int row = i >> 8, kl = i & 255;
    *(float4*)(As + i) =
        *(const float4*)(g_h + (b * 64 + row) * 1024 + z * 256 + kl);
  }
  stage_wsT(wsT, f2_w, 1024, c0, z * 256, tid);
  const int col = tid & 31;
  const int r0 = (tid >> 5) * 8;
  float acc[8];
#pragma unroll
  for (int r = 0; r < 8; r++) acc[r] = (z == 0) ? f2_b[c0 + col] : 0.f;
  __syncthreads();
  mid_core(As, wsT, acc, col, r0);
#pragma unroll
  for (int r = 0; r < 8; r++)
    g_f2p[z][(b * 64 + r0 + r) * 256 + c0 + col] = acc[r];
}

// ===========================================================================
// KC: decode out = W @ st2 + x via tf32 mma (unchanged)
// ===========================================================================
__global__ __launch_bounds__(256) void k_decode(const float* __restrict__ x,
                                                float* __restrict__ out) {
  extern __shared__ float sm[];
  float* st2s = sm;              // [64][SP]
  float* Ws = sm + 64 * SP;      // [128][AP]
  const int tid = threadIdx.x;
  const int b = blockIdx.y;
  const int n0 = blockIdx.x * 128;

  for (int i = tid * 4; i < 16384; i += 1024)
    *(float4*)(st2s + (i >> 8) * SP + (i & 255)) =
        *(const float4*)(g_st2 + b * 16384 + i);
  for (int i = tid * 4; i < 8192; i += 1024)
    *(float4*)(Ws + (i >> 6) * AP + (i & 63)) =
        *(const float4*)(g_W + ((size_t)b * NN + n0 + (i >> 6)) * 64 + (i & 63));
  __syncthreads();

  const int wid = tid >> 5, lane = tid & 31;
  const int r = lane >> 2, q = lane & 3;
  const int m0 = wid * 16;

  for (int nh = 0; nh < 2; nh++) {
    float acc[16][4];
#pragma unroll
    for (int i = 0; i < 16; i++)
#pragma unroll
      for (int j = 0; j < 4; j++) acc[i][j] = 0.f;

    for (int ks = 0; ks < 8; ks++) {
      const int k0 = ks * 8;
      uint32_t a0 = F2U(Ws[(m0 + r) * AP + k0 + q]);
      uint32_t a1 = F2U(Ws[(m0 + r + 8) * AP + k0 + q]);
      uint32_t a2 = F2U(Ws[(m0 + r) * AP + k0 + q + 4]);
      uint32_t a3 = F2U(Ws[(m0 + r + 8) * AP + k0 + q + 4]);
#pragma unroll
      for (int nt = 0; nt < 16; nt++) {
        const int n = nh * 128 + nt * 8;
        uint32_t b0 = F2U(st2s[(k0 + q) * SP + n + r]);
        uint32_t b1 = F2U(st2s[(k0 + q + 4) * SP + n + r]);
        mma_tf32(acc[nt], a0, a1, a2, a3, b0, b1);
      }
    }
#pragma unroll
    for (int nt = 0; nt < 16; nt++) {
      const int n = nh * 128 + nt * 8 + 2 * q;
      const size_t base0 = ((size_t)b * NN + n0 + m0 + r) * 256 + n;
      const size_t base1 = base0 + 8 * 256;
      float2 xv0 = *(const float2*)(x + base0);
      float2 xv1 = *(const float2*)(x + base1);
      *(float2*)(out + base0) = make_float2(acc[nt][0] + xv0.x, acc[nt][1] + xv0.y);
      *(float2*)(out + base1) = make_float2(acc[nt][2] + xv1.x, acc[nt][3] + xv1.y);
    }
  }
}

// ===========================================================================
extern "C" void kernel_launch(void* const* d_in, const int* in_sizes, int n_in,
                              void* d_out, int out_size) {
  const float* x = (const float*)d_in[0];
  const float* sq_w = (const float*)d_in[1];
  const float* sq_b = (const float*)d_in[2];
  const float* eid_state = (const float*)d_in[3];
  const float* eid_gw = (const float*)d_in[4];
  const float* eid_gb = (const float*)d_in[5];
  const float* in_w = (const float*)d_in[6];
  const float* in_b = (const float*)d_in[7];
  const float* out_w = (const float*)d_in[8];
  const float* out_b = (const float*)d_in[9];
  const float* n1_g = (const float*)d_in[10];
  const float* n1_b = (const float*)d_in[11];
  const float* n2_g = (const float*)d_in[12];
  const float* n2_b = (const float*)d_in[13];
  const float* f1_w = (const float*)d_in[14];
  const float* f1_b = (const float*)d_in[15];
  const float* f2_w = (const float*)d_in[16];
  const float* f2_b = (const float*)d_in[17];
  float* out = (float*)d_out;

  const int smem_ka = (64 * XP + 64 * WP + 64 * LP + 64) * 4;
  const int smem_kc = (64 * SP + 128 * AP) * 4;
  cudaFuncSetAttribute(k_assign_pool, cudaFuncAttributeMaxDynamicSharedMemorySize, smem_ka);
  cudaFuncSetAttribute(k_decode, cudaFuncAttributeMaxDynamicSharedMemorySize, smem_kc);
  cudaFuncSetAttribute(k_gate, cudaFuncAttributeMaxDynamicSharedMemorySize, MID_SMEM);
  cudaFuncSetAttribute(k_qkv, cudaFuncAttributeMaxDynamicSharedMemorySize, MID_SMEM);
  cudaFuncSetAttribute(k_proj, cudaFuncAttributeMaxDynamicSharedMemorySize, MID_SMEM);
  cudaFuncSetAttribute(k_ffn1, cudaFuncAttributeMaxDynamicSharedMemorySize, MID_SMEM);
  cudaFuncSetAttribute(k_ffn2, cudaFuncAttributeMaxDynamicSharedMemorySize, MID_SMEM);

  float *p_stg, *p_pro, *p_st1, *p_f2p, *p_st2;
  cudaGetSymbolAddress((void**)&p_stg, g_stg);
  cudaGetSymbolAddress((void**)&p_pro, g_pro);
  cudaGetSymbolAddress((void**)&p_st1, g_st1);
  cudaGetSymbolAddress((void**)&p_f2p, g_f2p);
  cudaGetSymbolAddress((void**)&p_st2, g_st2);

  k_assign_pool<<<dim3(128, BB), 256, smem_ka>>>(x, sq_w, sq_b);
  k_reduce_st<<<64, 256>>>();
  k_gate<<<dim3(8, BB), 256, MID_SMEM>>>(eid_gw, eid_gb, eid_state);
  k_qkv<<<dim3(24, BB), 256, MID_SMEM>>>(in_w, in_b);
  k_attn<<<32, 256>>>();
  k_proj<<<dim3(8, BB), 256, MID_SMEM>>>(out_w, out_b);
  k_ln<<<64, 256>>>(p_stg, p_pro, 1, n1_g, n1_b, p_st1);
  k_ffn1<<<dim3(32, BB), 256, MID_SMEM>>>(f1_w, f1_b);
  k_ffn2<<<dim3(8, BB, 4), 256, MID_SMEM>>>(f2_w, f2_b);
  k_ln<<<64, 256>>>(p_st1, p_f2p, 4, n2_g, n2_b, p_st2);
  k_decode<<<dim3(256, BB), 256, smem_kc>>>(x, out);
}

// round 8
// speedup vs baseline: 2.3943x; 1.2788x over previous
#include <cuda_runtime.h>
#include <stdint.h>
#include <math.h>

#define BB 4
#define NN 32768
#define HH 256
#define SS 64

#define XP 268   // xs row pad (floats)
#define WP 268   // sq_w row pad
#define LP 72    // logits/W tile row pad
#define SP 268   // st2 row pad (KC)
#define AP 68    // W tile row pad (KC)

// ---------------- scratch (static device allocations only) ----------------
__device__ float g_W[(size_t)BB * NN * SS];          // 32 MB soft-assignment weights
__device__ float g_part[(size_t)256 * 16384];        // 16.8MB pooling partials
__device__ float g_st[BB * SS * HH];
__device__ float g_stg[BB * SS * HH];                // gated st
__device__ float g_qkv[BB * SS * 3 * HH];
__device__ float g_ao[BB * SS * HH];
__device__ float g_pro[BB * SS * HH];                // attn out-proj (pre-LN)
__device__ float g_st1[BB * SS * HH];
__device__ float g_h[BB * SS * 4 * HH];
__device__ float g_f2p[4][BB * SS * HH];             // ffn2 k-split partials
__device__ float g_st2[BB * SS * HH];

// ---- m16n8k8 tf32 mma helper --------------------------------------------
__device__ __forceinline__ void mma_tf32(float c[4], uint32_t a0, uint32_t a1,
                                         uint32_t a2, uint32_t a3, uint32_t b0,
                                         uint32_t b1) {
  asm volatile(
      "mma.sync.aligned.m16n8k8.row.col.f32.tf32.tf32.f32 "
      "{%0,%1,%2,%3}, {%4,%5,%6,%7}, {%8,%9}, {%0,%1,%2,%3};\n"
      : "+f"(c[0]), "+f"(c[1]), "+f"(c[2]), "+f"(c[3])
      : "r"(a0), "r"(a1), "r"(a2), "r"(a3), "r"(b0), "r"(b1));
}
#define F2U __float_as_uint

// ===========================================================================
// KA: fused logits + softmax + pooling. 512 threads (16 warps), grid (64, B).
// 512 tokens per block in 8 tiles of 64.
// Phase A: warp = (m-tile, n-quarter), full K — no split-K reduction.
// Pooling: warp = 16-h tile, all 64 slots.
// ===========================================================================
__global__ __launch_bounds__(512) void k_assign_pool(
    const float* __restrict__ x, const float* __restrict__ sq_w,
    const float* __restrict__ sq_b) {
  extern __shared__ float sm[];
  float* xs = sm;                 // [64][XP]
  float* ws = sm + 64 * XP;       // [64][WP]
  float* lg = ws + 64 * WP;       // [64][LP]
  float* sb = lg + 64 * LP;       // [64]

  const int tid = threadIdx.x;
  const int b = blockIdx.y;
  const size_t tok0 = (size_t)blockIdx.x * 512;
  const float* xb = x + (size_t)b * NN * HH;

  for (int i = tid * 4; i < 16384; i += 2048) {
    float4 v = *(const float4*)(sq_w + i);
    *(float4*)(ws + (i >> 8) * WP + (i & 255)) = v;
  }
  if (tid < 64) sb[tid] = sq_b[tid];

  const int wid = tid >> 5, lane = tid & 31;
  const int r = lane >> 2, q = lane & 3;
  const int mA = (wid & 3) * 16;   // phase-A m-tile
  const int wn = wid >> 2;         // phase-A n-quarter (0..3)
  const int hb = wid * 16;         // pooling h tile

  float stacc[8][4];
#pragma unroll
  for (int j = 0; j < 8; j++)
#pragma unroll
    for (int k = 0; k < 4; k++) stacc[j][k] = 0.f;

  for (int tile = 0; tile < 8; tile++) {
    __syncthreads();  // previous tile's xs/lg consumers done
    const float* xsrc = xb + (tok0 + tile * 64) * 256;
    for (int i = tid * 4; i < 16384; i += 2048)
      *(float4*)(xs + (i >> 8) * XP + (i & 255)) = *(const float4*)(xsrc + i);
    __syncthreads();

    // ---- phase A: logits, full K=256, 2 n-tiles per warp ----
    float lacc[2][4];
#pragma unroll
    for (int j = 0; j < 2; j++)
#pragma unroll
      for (int k = 0; k < 4; k++) lacc[j][k] = 0.f;

    for (int ks = 0; ks < 32; ks++) {
      const int k0 = ks * 8;
      uint32_t a0 = F2U(xs[(mA + r) * XP + k0 + q]);
      uint32_t a1 = F2U(xs[(mA + r + 8) * XP + k0 + q]);
      uint32_t a2 = F2U(xs[(mA + r) * XP + k0 + q + 4]);
      uint32_t a3 = F2U(xs[(mA + r + 8) * XP + k0 + q + 4]);
#pragma unroll
      for (int j = 0; j < 2; j++) {
        const int nt = wn * 2 + j;
        uint32_t b0 = F2U(ws[(nt * 8 + r) * WP + k0 + q]);
        uint32_t b1 = F2U(ws[(nt * 8 + r) * WP + k0 + q + 4]);
        mma_tf32(lacc[j], a0, a1, a2, a3, b0, b1);
      }
    }
#pragma unroll
    for (int j = 0; j < 2; j++) {
      const int nt = wn * 2 + j;
      lg[(mA + r) * LP + nt * 8 + 2 * q] = lacc[j][0];
      lg[(mA + r) * LP + nt * 8 + 2 * q + 1] = lacc[j][1];
      lg[(mA + r + 8) * LP + nt * 8 + 2 * q] = lacc[j][2];
      lg[(mA + r + 8) * LP + nt * 8 + 2 * q + 1] = lacc[j][3];
    }
    __syncthreads();

    // ---- softmax: 8 threads per row ----
    {
      const int t = tid >> 3, qq = tid & 7;
      float v[8];
      float mx = -1e30f;
#pragma unroll
      for (int i = 0; i < 8; i++) {
        v[i] = lg[t * LP + qq * 8 + i] + sb[qq * 8 + i];
        mx = fmaxf(mx, v[i]);
      }
      mx = fmaxf(mx, __shfl_xor_sync(0xffffffffu, mx, 1));
      mx = fmaxf(mx, __shfl_xor_sync(0xffffffffu, mx, 2));
      mx = fmaxf(mx, __shfl_xor_sync(0xffffffffu, mx, 4));
      float s = 0.f;
#pragma unroll
      for (int i = 0; i < 8; i++) {
        v[i] = __expf(v[i] - mx);
        s += v[i];
      }
      s += __shfl_xor_sync(0xffffffffu, s, 1);
      s += __shfl_xor_sync(0xffffffffu, s, 2);
      s += __shfl_xor_sync(0xffffffffu, s, 4);
      const float inv = 1.f / s;
      const size_t wrow =
          ((size_t)b * NN + tok0 + tile * 64 + t) * 64 + qq * 8;
#pragma unroll
      for (int i = 0; i < 8; i++) {
        float w = v[i] * inv;
        lg[t * LP + qq * 8 + i] = w;
        g_W[wrow + i] = w;
      }
    }
    __syncthreads();

    // ---- pooling: st^T[h][s] += x^T @ Wtile, warp = 16 h rows ----
    for (int ks = 0; ks < 8; ks++) {
      const int k0 = ks * 8;
      uint32_t a0 = F2U(xs[(k0 + q) * XP + hb + r]);
      uint32_t a1 = F2U(xs[(k0 + q) * XP + hb + r + 8]);
      uint32_t a2 = F2U(xs[(k0 + q + 4) * XP + hb + r]);
      uint32_t a3 = F2U(xs[(k0 + q + 4) * XP + hb + r + 8]);
#pragma unroll
      for (int nt = 0; nt < 8; nt++) {
        uint32_t b0 = F2U(lg[(k0 + q) * LP + nt * 8 + r]);
        uint32_t b1 = F2U(lg[(k0 + q + 4) * LP + nt * 8 + r]);
        mma_tf32(stacc[nt], a0, a1, a2, a3, b0, b1);
      }
    }
  }

  float* pp = g_part + (size_t)(b * 64 + blockIdx.x) * 16384;
#pragma unroll
  for (int nt = 0; nt < 8; nt++) {
    const int h0 = hb + r;
    const int s0 = nt * 8 + 2 * q;
    *(float2*)(pp + h0 * 64 + s0) = make_float2(stacc[nt][0], stacc[nt][1]);
    *(float2*)(pp + (h0 + 8) * 64 + s0) = make_float2(stacc[nt][2], stacc[nt][3]);
  }
}

// ===========================================================================
// reduce pooling partials (64 per batch) -> g_st
// ===========================================================================
__global__ __launch_bounds__(256) void k_reduce_st() {
  const int gt = blockIdx.x * 256 + threadIdx.x;  // 0..16383
  const int bb = gt >> 12;
  const int p4 = (gt & 4095) * 4;
  const float* p = g_part + (size_t)bb * 64 * 16384 + p4;
  float4 acc = make_float4(0.f, 0.f, 0.f, 0.f);
#pragma unroll 8
  for (int j = 0; j < 64; j++) {
    float4 v = *(const float4*)(p + (size_t)j * 16384);
    acc.x += v.x; acc.y += v.y; acc.z += v.z; acc.w += v.w;
  }
  const int h = p4 >> 6, s0 = p4 & 63;
  float* dst = g_st + bb * 16384 + h;
  dst[(s0 + 0) * 256] = acc.x;
  dst[(s0 + 1) * 256] = acc.y;
  dst[(s0 + 2) * 256] = acc.z;
  dst[(s0 + 3) * 256] = acc.w;
}

// ===========================================================================
// Middle GEMM core, 1024 threads (32 warps).
// smem: As[64][256] + wsT4 (float4)[64][33].
// thread = 1 col x 2 rows; weights read as float4 per 4-k chunk.
// ===========================================================================
#define MID_SMEM ((64 * 256 + 64 * 33 * 4) * 4)

__device__ __forceinline__ void stage_as(float* As, const float* src, int tid) {
  for (int i = tid * 4; i < 16384; i += 4096)
    *(float4*)(As + i) = *(const float4*)(src + i);
}

__device__ __forceinline__ void stage_wsT4(float4* wsT4, const float* w,
                                           int ldw, int c0, int koff, int tid) {
  for (int i = tid * 4; i < 32 * 256; i += 4096) {
    int cl = i >> 8, k = i & 255;
    float4 v = *(const float4*)(w + (size_t)(c0 + cl) * ldw + koff + k);
    wsT4[(k >> 2) * 33 + cl] = v;
  }
}

__device__ __forceinline__ void mid_core(const float* __restrict__ As,
                                         const float4* __restrict__ wsT4,
                                         float acc[2], int col, int r0) {
#pragma unroll 8
  for (int k = 0; k < 64; k++) {
    float4 w = wsT4[k * 33 + col];
    float4 a0 = *(const float4*)(As + r0 * 256 + k * 4);
    float4 a1 = *(const float4*)(As + (r0 + 1) * 256 + k * 4);
    acc[0] += a0.x * w.x + a0.y * w.y + a0.z * w.z + a0.w * w.w;
    acc[1] += a1.x * w.x + a1.y * w.y + a1.z * w.z + a1.w * w.w;
  }
}

// gate: st_gated = st + sigmoid(st @ gw^T + gb) * estate
__global__ __launch_bounds__(1024) void k_gate(
    const float* __restrict__ gw, const float* __restrict__ gb,
    const float* __restrict__ estate) {
  extern __shared__ float smm[];
  float* As = smm;
  float4* wsT4 = (float4*)(smm + 64 * 256);
  const int tid = threadIdx.x;
  const int b = blockIdx.y;
  const int c0 = blockIdx.x * 32;
  stage_as(As, g_st + b * 16384, tid);
  stage_wsT4(wsT4, gw, 256, c0, 0, tid);
  const int col = tid & 31;
  const int r0 = (tid >> 5) * 2;
  float acc[2] = {gb[c0 + col], gb[c0 + col]};
  __syncthreads();
  mid_core(As, wsT4, acc, col, r0);
#pragma unroll
  for (int r = 0; r < 2; r++) {
    const int s = r0 + r;
    float gate = 1.f / (1.f + expf(-acc[r]));
    g_stg[b * 16384 + s * 256 + c0 + col] =
        As[s * 256 + c0 + col] + gate * estate[s * 256 + c0 + col];
  }
}

__global__ __launch_bounds__(1024) void k_qkv(
    const float* __restrict__ in_w, const float* __restrict__ in_b) {
  extern __shared__ float smm[];
  float* As = smm;
  float4* wsT4 = (float4*)(smm + 64 * 256);
  const int tid = threadIdx.x;
  const int b = blockIdx.y;
  const int c0 = blockIdx.x * 32;
  stage_as(As, g_stg + b * 16384, tid);
  stage_wsT4(wsT4, in_w, 256, c0, 0, tid);
  const int col = tid & 31;
  const int r0 = (tid >> 5) * 2;
  float acc[2] = {in_b[c0 + col], in_b[c0 + col]};
  __syncthreads();
  mid_core(As, wsT4, acc, col, r0);
#pragma unroll
  for (int r = 0; r < 2; r++)
    g_qkv[(b * 64 + r0 + r) * 768 + c0 + col] = acc[r];
}

// attention per (b, head): 32 blocks, 1024 threads
__global__ __launch_bounds__(1024) void k_attn() {
  int b = blockIdx.x >> 3, hh = blockIdx.x & 7;
  __shared__ float q[64][32], kk[64][33], vv[64][32], p[64][65];
  int tid = threadIdx.x;
  for (int i = tid; i < 2048; i += 1024) {
    int s = i >> 5, d = i & 31;
    int base = (b * 64 + s) * 768 + hh * 32 + d;
    q[s][d] = g_qkv[base];
    kk[s][d] = g_qkv[base + 256];
    vv[s][d] = g_qkv[base + 512];
  }
  __syncthreads();
  for (int idx = tid; idx < 4096; idx += 1024) {
    int qi = idx >> 6, ki = idx & 63;
    float a = 0.f;
#pragma unroll
    for (int d = 0; d < 32; d++) a += q[qi][d] * kk[ki][d];
    p[qi][ki] = a * 0.17677669529663687f;
  }
  __syncthreads();
  if (tid < 512) {
    const int row = tid >> 3, qq = tid & 7;
    float v[8], mx = -1e30f;
#pragma unroll
    for (int i = 0; i < 8; i++) {
      v[i] = p[row][qq * 8 + i];
      mx = fmaxf(mx, v[i]);
    }
    mx = fmaxf(mx, __shfl_xor_sync(0xffffffffu, mx, 1));
    mx = fmaxf(mx, __shfl_xor_sync(0xffffffffu, mx, 2));
    mx = fmaxf(mx, __shfl_xor_sync(0xffffffffu, mx, 4));
    float s = 0.f;
#pragma unroll
    for (int i = 0; i < 8; i++) { v[i] = __expf(v[i] - mx); s += v[i]; }
    s += __shfl_xor_sync(0xffffffffu, s, 1);
    s += __shfl_xor_sync(0xffffffffu, s, 2);
    s += __shfl_xor_sync(0xffffffffu, s, 4);
    const float inv = 1.f / s;
#pragma unroll
    for (int i = 0; i < 8; i++) p[row][qq * 8 + i] = v[i] * inv;
  }
  __syncthreads();
  for (int idx = tid; idx < 2048; idx += 1024) {
    int qi = idx >> 5, d = idx & 31;
    float a = 0.f;
#pragma unroll
    for (int j = 0; j < 64; j++) a += p[qi][j] * vv[j][d];
    g_ao[(b * 64 + qi) * 256 + hh * 32 + d] = a;
  }
}

__global__ __launch_bounds__(1024) void k_proj(
    const float* __restrict__ out_w, const float* __restrict__ out_b) {
  extern __shared__ float smm[];
  float* As = smm;
  float4* wsT4 = (float4*)(smm + 64 * 256);
  const int tid = threadIdx.x;
  const int b = blockIdx.y;
  const int c0 = blockIdx.x * 32;
  stage_as(As, g_ao + b * 16384, tid);
  stage_wsT4(wsT4, out_w, 256, c0, 0, tid);
  const int col = tid & 31;
  const int r0 = (tid >> 5) * 2;
  float acc[2] = {out_b[c0 + col], out_b[c0 + col]};
  __syncthreads();
  mid_core(As, wsT4, acc, col, r0);
#pragma unroll
  for (int r = 0; r < 2; r++)
    g_pro[(b * 64 + r0 + r) * 256 + c0 + col] = acc[r];
}

// LN: out = LN(a + sum of np partials)
__device__ __forceinline__ void ln4_reduce(float yv[4], float mu[4], float var[4],
                                           float wsum[4][8], float wsq[4][8],
                                           int tid) {
  float s1[4], s2[4];
#pragma unroll
  for (int r = 0; r < 4; r++) { s1[r] = yv[r]; s2[r] = yv[r] * yv[r]; }
#pragma unroll
  for (int off = 16; off; off >>= 1)
#pragma unroll
    for (int r = 0; r < 4; r++) {
      s1[r] += __shfl_xor_sync(0xffffffffu, s1[r], off);
      s2[r] += __shfl_xor_sync(0xffffffffu, s2[r], off);
    }
  int w = tid >> 5, lane = tid & 31;
  if (lane == 0)
#pragma unroll
    for (int r = 0; r < 4; r++) { wsum[r][w] = s1[r]; wsq[r][w] = s2[r]; }
  __syncthreads();
#pragma unroll
  for (int r = 0; r < 4; r++) {
    float a = 0.f, bq = 0.f;
#pragma unroll
    for (int ww = 0; ww < 8; ww++) { a += wsum[r][ww]; bq += wsq[r][ww]; }
    mu[r] = a * (1.f / 256.f);
    var[r] = bq * (1.f / 256.f) - mu[r] * mu[r];
  }
}

__global__ __launch_bounds__(256) void k_ln(
    const float* __restrict__ a, const float* __restrict__ parts, int np,
    const float* __restrict__ g, const float* __restrict__ bb,
    float* __restrict__ out) {
  int bs0 = blockIdx.x * 4;
  __shared__ float wsum[4][8], wsq[4][8];
  int tid = threadIdx.x;
  float yv[4];
#pragma unroll
  for (int r = 0; r < 4; r++) {
    int idx = (bs0 + r) * 256 + tid;
    float v = a[idx];
    for (int pz = 0; pz < np; pz++) v += parts[pz * (BB * SS * HH) + idx];
    yv[r] = v;
  }
  float mu[4], var[4];
  ln4_reduce(yv, mu, var, wsum, wsq, tid);
#pragma unroll
  for (int r = 0; r < 4; r++)
    out[(bs0 + r) * 256 + tid] =
        (yv[r] - mu[r]) * rsqrtf(var[r] + 1e-5f) * g[tid] + bb[tid];
}

// ffn1: 1024 outputs, GELU
__global__ __launch_bounds__(1024) void k_ffn1(
    const float* __restrict__ f1_w, const float* __restrict__ f1_b) {
  extern __shared__ float smm[];
  float* As = smm;
  float4* wsT4 = (float4*)(smm + 64 * 256);
  const int tid = threadIdx.x;
  const int b = blockIdx.y;
  const int c0 = blockIdx.x * 32;
  stage_as(As, g_st1 + b * 16384, tid);
  stage_wsT4(wsT4, f1_w, 256, c0, 0, tid);
  const int col = tid & 31;
  const int r0 = (tid >> 5) * 2;
  float acc[2] = {f1_b[c0 + col], f1_b[c0 + col]};
  __syncthreads();
  mid_core(As, wsT4, acc, col, r0);
#pragma unroll
  for (int r = 0; r < 2; r++) {
    float v = acc[r];
    g_h[(b * 64 + r0 + r) * 1024 + c0 + col] =
        0.5f * v * (1.f + erff(v * 0.7071067811865475f));
  }
}

// ffn2: K=1024 with 4-way k-split (blockIdx.z)
__global__ __launch_bounds__(1024) void k_ffn2(
    const float* __restrict__ f2_w, const float* __restrict__ f2_b) {
  extern __shared__ float smm[];
  float* As = smm;
  float4* wsT4 = (float4*)(smm + 64 * 256);
  const int tid = threadIdx.x;
  const int b = blockIdx.y;
  const int z = blockIdx.z;
  const int c0 = blockIdx.x * 32;
  for (int i = tid * 4; i < 16384; i += 4096) {
    int row = i >> 8, kl = i & 255;
    *(float4*)(As + i) =
        *(const float4*)(g_h + (b * 64 + row) * 1024 + z * 256 + kl);
  }
  stage_wsT4(wsT4, f2_w, 1024, c0, z * 256, tid);
  const int col = tid & 31;
  const int r0 = (tid >> 5) * 2;
  float bias = (z == 0) ? f2_b[c0 + col] : 0.f;
  float acc[2] = {bias, bias};
  __syncthreads();
  mid_core(As, wsT4, acc, col, r0);
#pragma unroll
  for (int r = 0; r < 2; r++)
    g_f2p[z][(b * 64 + r0 + r) * 256 + c0 + col] = acc[r];
}

// ===========================================================================
// KC: decode out = W @ st2 + x via tf32 mma. 512 threads, 256 tokens/block.
// grid (128, B). smem: st2s [64][SP] + Ws [256][AP] = 138KB.
// ===========================================================================
__global__ __launch_bounds__(512) void k_decode(const float* __restrict__ x,
                                                float* __restrict__ out) {
  extern __shared__ float sm[];
  float* st2s = sm;              // [64][SP]
  float* Ws = sm + 64 * SP;      // [256][AP]
  const int tid = threadIdx.x;
  const int b = blockIdx.y;
  const int n0 = blockIdx.x * 256;

  for (int i = tid * 4; i < 16384; i += 2048)
    *(float4*)(st2s + (i >> 8) * SP + (i & 255)) =
        *(const float4*)(g_st2 + b * 16384 + i);
  for (int i = tid * 4; i < 16384; i += 2048)
    *(float4*)(Ws + (i >> 6) * AP + (i & 63)) =
        *(const float4*)(g_W + ((size_t)b * NN + n0 + (i >> 6)) * 64 + (i & 63));
  __syncthreads();

  const int wid = tid >> 5, lane = tid & 31;
  const int r = lane >> 2, q = lane & 3;
  const int m0 = wid * 16;

  for (int nh = 0; nh < 2; nh++) {
    float acc[16][4];
#pragma unroll
    for (int i = 0; i < 16; i++)
#pragma unroll
      for (int j = 0; j < 4; j++) acc[i][j] = 0.f;

    for (int ks = 0; ks < 8; ks++) {
      const int k0 = ks * 8;
      uint32_t a0 = F2U(Ws[(m0 + r) * AP + k0 + q]);
      uint32_t a1 = F2U(Ws[(m0 + r + 8) * AP + k0 + q]);
      uint32_t a2 = F2U(Ws[(m0 + r) * AP + k0 + q + 4]);
      uint32_t a3 = F2U(Ws[(m0 + r + 8) * AP + k0 + q + 4]);
#pragma unroll
      for (int nt = 0; nt < 16; nt++) {
        const int n = nh * 128 + nt * 8;
        uint32_t b0 = F2U(st2s[(k0 + q) * SP + n + r]);
        uint32_t b1 = F2U(st2s[(k0 + q + 4) * SP + n + r]);
        mma_tf32(acc[nt], a0, a1, a2, a3, b0, b1);
      }
    }
#pragma unroll
    for (int nt = 0; nt < 16; nt++) {
      const int n = nh * 128 + nt * 8 + 2 * q;
      const size_t base0 = ((size_t)b * NN + n0 + m0 + r) * 256 + n;
      const size_t base1 = base0 + 8 * 256;
      float2 xv0 = *(const float2*)(x + base0);
      float2 xv1 = *(const float2*)(x + base1);
      *(float2*)(out + base0) = make_float2(acc[nt][0] + xv0.x, acc[nt][1] + xv0.y);
      *(float2*)(out + base1) = make_float2(acc[nt][2] + xv1.x, acc[nt][3] + xv1.y);
    }
  }
}

// ===========================================================================
extern "C" void kernel_launch(void* const* d_in, const int* in_sizes, int n_in,
                              void* d_out, int out_size) {
  const float* x = (const float*)d_in[0];
  const float* sq_w = (const float*)d_in[1];
  const float* sq_b = (const float*)d_in[2];
  const float* eid_state = (const float*)d_in[3];
  const float* eid_gw = (const float*)d_in[4];
  const float* eid_gb = (const float*)d_in[5];
  const float* in_w = (const float*)d_in[6];
  const float* in_b = (const float*)d_in[7];
  const float* out_w = (const float*)d_in[8];
  const float* out_b = (const float*)d_in[9];
  const float* n1_g = (const float*)d_in[10];
  const float* n1_b = (const float*)d_in[11];
  const float* n2_g = (const float*)d_in[12];
  const float* n2_b = (const float*)d_in[13];
  const float* f1_w = (const float*)d_in[14];
  const float* f1_b = (const float*)d_in[15];
  const float* f2_w = (const float*)d_in[16];
  const float* f2_b = (const float*)d_in[17];
  float* out = (float*)d_out;

  const int smem_ka = (64 * XP + 64 * WP + 64 * LP + 64) * 4;
  const int smem_kc = (64 * SP + 256 * AP) * 4;
  cudaFuncSetAttribute(k_assign_pool, cudaFuncAttributeMaxDynamicSharedMemorySize, smem_ka);
  cudaFuncSetAttribute(k_decode, cudaFuncAttributeMaxDynamicSharedMemorySize, smem_kc);
  cudaFuncSetAttribute(k_gate, cudaFuncAttributeMaxDynamicSharedMemorySize, MID_SMEM);
  cudaFuncSetAttribute(k_qkv, cudaFuncAttributeMaxDynamicSharedMemorySize, MID_SMEM);
  cudaFuncSetAttribute(k_proj, cudaFuncAttributeMaxDynamicSharedMemorySize, MID_SMEM);
  cudaFuncSetAttribute(k_ffn1, cudaFuncAttributeMaxDynamicSharedMemorySize, MID_SMEM);
  cudaFuncSetAttribute(k_ffn2, cudaFuncAttributeMaxDynamicSharedMemorySize, MID_SMEM);

  float *p_stg, *p_pro, *p_st1, *p_f2p, *p_st2;
  cudaGetSymbolAddress((void**)&p_stg, g_stg);
  cudaGetSymbolAddress((void**)&p_pro, g_pro);
  cudaGetSymbolAddress((void**)&p_st1, g_st1);
  cudaGetSymbolAddress((void**)&p_f2p, g_f2p);
  cudaGetSymbolAddress((void**)&p_st2, g_st2);

  k_assign_pool<<<dim3(64, BB), 512, smem_ka>>>(x, sq_w, sq_b);
  k_reduce_st<<<64, 256>>>();
  k_gate<<<dim3(8, BB), 1024, MID_SMEM>>>(eid_gw, eid_gb, eid_state);
  k_qkv<<<dim3(24, BB), 1024, MID_SMEM>>>(in_w, in_b);
  k_attn<<<32, 1024>>>();
  k_proj<<<dim3(8, BB), 1024, MID_SMEM>>>(out_w, out_b);
  k_ln<<<64, 256>>>(p_stg, p_pro, 1, n1_g, n1_b, p_st1);
  k_ffn1<<<dim3(32, BB), 1024, MID_SMEM>>>(f1_w, f1_b);
  k_ffn2<<<dim3(8, BB, 4), 1024, MID_SMEM>>>(f2_w, f2_b);
  k_ln<<<64, 256>>>(p_st1, p_f2p, 4, n2_g, n2_b, p_st2);
  k_decode<<<dim3(128, BB), 512, smem_kc>>>(x, out);
}

// round 9
// speedup vs baseline: 2.6970x; 1.1264x over previous
#include <cuda_runtime.h>
#include <stdint.h>
#include <math.h>

#define BB 4
#define NN 32768
#define HH 256
#define SS 64

#define XP 268   // xs row pad (floats)
#define WP 268   // sq_w row pad
#define LP 72    // logits/W tile row pad
#define SP 268   // st2 row pad (KC)
#define AP 68    // W tile row pad (KC)
#define MP 268   // middle-gemm row pad

// ---------------- scratch (static device allocations only) ----------------
__device__ float g_W[(size_t)BB * NN * SS];          // 32 MB soft-assignment weights
__device__ float g_part[(size_t)256 * 16384];        // 16.8MB pooling partials
__device__ float g_st[BB * SS * HH];
__device__ float g_stg[BB * SS * HH];                // gated st
__device__ float g_qkv[BB * SS * 3 * HH];
__device__ float g_ao[BB * SS * HH];
__device__ float g_pro[BB * SS * HH];                // attn out-proj (pre-LN)
__device__ float g_st1[BB * SS * HH];
__device__ float g_h[BB * SS * 4 * HH];
__device__ float g_f2p[4][BB * SS * HH];             // ffn2 k-split partials
__device__ float g_st2[BB * SS * HH];

// ---- m16n8k8 tf32 mma helper --------------------------------------------
__device__ __forceinline__ void mma_tf32(float c[4], uint32_t a0, uint32_t a1,
                                         uint32_t a2, uint32_t a3, uint32_t b0,
                                         uint32_t b1) {
  asm volatile(
      "mma.sync.aligned.m16n8k8.row.col.f32.tf32.tf32.f32 "
      "{%0,%1,%2,%3}, {%4,%5,%6,%7}, {%8,%9}, {%0,%1,%2,%3};\n"
      : "+f"(c[0]), "+f"(c[1]), "+f"(c[2]), "+f"(c[3])
      : "r"(a0), "r"(a1), "r"(a2), "r"(a3), "r"(b0), "r"(b1));
}
#define F2U __float_as_uint

// ===========================================================================
// KA: fused logits + softmax + pooling. 512 threads, grid (64, B).
// 512 tokens per block in 8 tiles of 64. x staging double-buffered via regs.
// ===========================================================================
__global__ __launch_bounds__(512, 1) void k_assign_pool(
    const float* __restrict__ x, const float* __restrict__ sq_w,
    const float* __restrict__ sq_b) {
  extern __shared__ float sm[];
  float* xs = sm;                 // [64][XP]
  float* ws = sm + 64 * XP;       // [64][WP]
  float* lg = ws + 64 * WP;       // [64][LP]
  float* sb = lg + 64 * LP;       // [64]

  const int tid = threadIdx.x;
  const int b = blockIdx.y;
  const size_t tok0 = (size_t)blockIdx.x * 512;
  const float* xb = x + (size_t)b * NN * HH;

  for (int i = tid * 4; i < 16384; i += 2048) {
    float4 v = *(const float4*)(sq_w + i);
    *(float4*)(ws + (i >> 8) * WP + (i & 255)) = v;
  }
  if (tid < 64) sb[tid] = sq_b[tid];

  const int wid = tid >> 5, lane = tid & 31;
  const int r = lane >> 2, q = lane & 3;
  const int mA = (wid & 3) * 16;   // phase-A m-tile
  const int wn = wid >> 2;         // phase-A n-quarter (0..3)
  const int hb = wid * 16;         // pooling h tile

  float stacc[8][4];
#pragma unroll
  for (int j = 0; j < 8; j++)
#pragma unroll
    for (int k = 0; k < 4; k++) stacc[j][k] = 0.f;

  // prefetch tile 0 into registers
  float4 pf[8];
  {
    const float* xsrc = xb + tok0 * 256;
#pragma unroll
    for (int it = 0; it < 8; it++)
      pf[it] = *(const float4*)(xsrc + tid * 4 + it * 2048);
  }

  for (int tile = 0; tile < 8; tile++) {
    __syncthreads();  // previous tile's xs/lg consumers done
#pragma unroll
    for (int it = 0; it < 8; it++) {
      const int i = tid * 4 + it * 2048;
      *(float4*)(xs + (i >> 8) * XP + (i & 255)) = pf[it];
    }
    __syncthreads();
    if (tile < 7) {  // issue next tile's loads; overlap with compute below
      const float* xsrc = xb + (tok0 + (tile + 1) * 64) * 256;
#pragma unroll
      for (int it = 0; it < 8; it++)
        pf[it] = *(const float4*)(xsrc + tid * 4 + it * 2048);
    }

    // ---- phase A: logits, full K=256, 2 n-tiles per warp ----
    float lacc[2][4];
#pragma unroll
    for (int j = 0; j < 2; j++)
#pragma unroll
      for (int k = 0; k < 4; k++) lacc[j][k] = 0.f;

    for (int ks = 0; ks < 32; ks++) {
      const int k0 = ks * 8;
      uint32_t a0 = F2U(xs[(mA + r) * XP + k0 + q]);
      uint32_t a1 = F2U(xs[(mA + r + 8) * XP + k0 + q]);
      uint32_t a2 = F2U(xs[(mA + r) * XP + k0 + q + 4]);
      uint32_t a3 = F2U(xs[(mA + r + 8) * XP + k0 + q + 4]);
#pragma unroll
      for (int j = 0; j < 2; j++) {
        const int nt = wn * 2 + j;
        uint32_t b0 = F2U(ws[(nt * 8 + r) * WP + k0 + q]);
        uint32_t b1 = F2U(ws[(nt * 8 + r) * WP + k0 + q + 4]);
        mma_tf32(lacc[j], a0, a1, a2, a3, b0, b1);
      }
    }
#pragma unroll
    for (int j = 0; j < 2; j++) {
      const int nt = wn * 2 + j;
      lg[(mA + r) * LP + nt * 8 + 2 * q] = lacc[j][0];
      lg[(mA + r) * LP + nt * 8 + 2 * q + 1] = lacc[j][1];
      lg[(mA + r + 8) * LP + nt * 8 + 2 * q] = lacc[j][2];
      lg[(mA + r + 8) * LP + nt * 8 + 2 * q + 1] = lacc[j][3];
    }
    __syncthreads();

    // ---- softmax: 8 threads per row ----
    {
      const int t = tid >> 3, qq = tid & 7;
      float v[8];
      float mx = -1e30f;
#pragma unroll
      for (int i = 0; i < 8; i++) {
        v[i] = lg[t * LP + qq * 8 + i] + sb[qq * 8 + i];
        mx = fmaxf(mx, v[i]);
      }
      mx = fmaxf(mx, __shfl_xor_sync(0xffffffffu, mx, 1));
      mx = fmaxf(mx, __shfl_xor_sync(0xffffffffu, mx, 2));
      mx = fmaxf(mx, __shfl_xor_sync(0xffffffffu, mx, 4));
      float s = 0.f;
#pragma unroll
      for (int i = 0; i < 8; i++) {
        v[i] = __expf(v[i] - mx);
        s += v[i];
      }
      s += __shfl_xor_sync(0xffffffffu, s, 1);
      s += __shfl_xor_sync(0xffffffffu, s, 2);
      s += __shfl_xor_sync(0xffffffffu, s, 4);
      const float inv = 1.f / s;
      const size_t wrow =
          ((size_t)b * NN + tok0 + tile * 64 + t) * 64 + qq * 8;
#pragma unroll
      for (int i = 0; i < 8; i++) {
        float w = v[i] * inv;
        lg[t * LP + qq * 8 + i] = w;
        g_W[wrow + i] = w;
      }
    }
    __syncthreads();

    // ---- pooling: st^T[h][s] += x^T @ Wtile, warp = 16 h rows ----
    for (int ks = 0; ks < 8; ks++) {
      const int k0 = ks * 8;
      uint32_t a0 = F2U(xs[(k0 + q) * XP + hb + r]);
      uint32_t a1 = F2U(xs[(k0 + q) * XP + hb + r + 8]);
      uint32_t a2 = F2U(xs[(k0 + q + 4) * XP + hb + r]);
      uint32_t a3 = F2U(xs[(k0 + q + 4) * XP + hb + r + 8]);
#pragma unroll
      for (int nt = 0; nt < 8; nt++) {
        uint32_t b0 = F2U(lg[(k0 + q) * LP + nt * 8 + r]);
        uint32_t b1 = F2U(lg[(k0 + q + 4) * LP + nt * 8 + r]);
        mma_tf32(stacc[nt], a0, a1, a2, a3, b0, b1);
      }
    }
  }

  float* pp = g_part + (size_t)(b * 64 + blockIdx.x) * 16384;
#pragma unroll
  for (int nt = 0; nt < 8; nt++) {
    const int h0 = hb + r;
    const int s0 = nt * 8 + 2 * q;
    *(float2*)(pp + h0 * 64 + s0) = make_float2(stacc[nt][0], stacc[nt][1]);
    *(float2*)(pp + (h0 + 8) * 64 + s0) = make_float2(stacc[nt][2], stacc[nt][3]);
  }
}

// ===========================================================================
// reduce pooling partials (64 per batch) -> g_st
// ===========================================================================
__global__ __launch_bounds__(256) void k_reduce_st() {
  const int gt = blockIdx.x * 256 + threadIdx.x;  // 0..16383
  const int bb = gt >> 12;
  const int p4 = (gt & 4095) * 4;
  const float* p = g_part + (size_t)bb * 64 * 16384 + p4;
  float4 acc = make_float4(0.f, 0.f, 0.f, 0.f);
#pragma unroll 8
  for (int j = 0; j < 64; j++) {
    float4 v = *(const float4*)(p + (size_t)j * 16384);
    acc.x += v.x; acc.y += v.y; acc.z += v.z; acc.w += v.w;
  }
  const int h = p4 >> 6, s0 = p4 & 63;
  float* dst = g_st + bb * 16384 + h;
  dst[(s0 + 0) * 256] = acc.x;
  dst[(s0 + 1) * 256] = acc.y;
  dst[(s0 + 2) * 256] = acc.z;
  dst[(s0 + 3) * 256] = acc.w;
}

// ===========================================================================
// Middle GEMM via tf32 mma. 512 threads (16 warps).
// smem: As[64][MP] (activations, full 256-wide rows) + ws[32][MP] (32 weight
// rows for this block's output columns). warp = (m-tile 16) x (n-tile 8).
// ===========================================================================
#define MIDQ_SMEM ((64 * MP + 32 * MP) * 4)

__device__ __forceinline__ void stage_mid(float* As, float* ws,
                                          const float* asrc, int lds,
                                          const float* w, int ldw, int c0,
                                          int koff, int tid) {
  for (int i = tid * 4; i < 16384; i += 2048) {
    float4 v = *(const float4*)(asrc + (i >> 8) * lds + (i & 255));
    *(float4*)(As + (i >> 8) * MP + (i & 255)) = v;
  }
  for (int i = tid * 4; i < 8192; i += 2048) {
    int cl = i >> 8, k = i & 255;
    float4 v = *(const float4*)(w + (size_t)(c0 + cl) * ldw + koff + k);
    *(float4*)(ws + cl * MP + k) = v;
  }
}

__device__ __forceinline__ void mid_mma(const float* __restrict__ As,
                                        const float* __restrict__ ws,
                                        float c[4], int mA, int nq, int r,
                                        int q) {
#pragma unroll 4
  for (int ks = 0; ks < 32; ks++) {
    const int k0 = ks * 8;
    uint32_t a0 = F2U(As[(mA + r) * MP + k0 + q]);
    uint32_t a1 = F2U(As[(mA + r + 8) * MP + k0 + q]);
    uint32_t a2 = F2U(As[(mA + r) * MP + k0 + q + 4]);
    uint32_t a3 = F2U(As[(mA + r + 8) * MP + k0 + q + 4]);
    uint32_t b0 = F2U(ws[(nq * 8 + r) * MP + k0 + q]);
    uint32_t b1 = F2U(ws[(nq * 8 + r) * MP + k0 + q + 4]);
    mma_tf32(c, a0, a1, a2, a3, b0, b1);
  }
}

// thread->output mapping shared by all middle kernels
#define MID_PROLOG                                     \
  const int tid = threadIdx.x;                         \
  const int b = blockIdx.y;                            \
  const int c0 = blockIdx.x * 32;                      \
  const int wid = tid >> 5, lane = tid & 31;           \
  const int r = lane >> 2, q = lane & 3;               \
  const int mA = (wid & 3) * 16, nq = wid >> 2;        \
  const int cg = c0 + nq * 8 + 2 * q;                  \
  const int row0 = mA + r, row1 = mA + r + 8;

// gate: st_gated = st + sigmoid(st @ gw^T + gb) * estate
__global__ __launch_bounds__(512) void k_gate(
    const float* __restrict__ gw, const float* __restrict__ gb,
    const float* __restrict__ estate) {
  extern __shared__ float smm[];
  float* As = smm;
  float* ws = smm + 64 * MP;
  MID_PROLOG
  stage_mid(As, ws, g_st + b * 16384, 256, gw, 256, c0, 0, tid);
  float b0v = gb[cg], b1v = gb[cg + 1];
  float c[4] = {b0v, b1v, b0v, b1v};
  __syncthreads();
  mid_mma(As, ws, c, mA, nq, r, q);
  float s0 = 1.f / (1.f + __expf(-c[0]));
  float s1 = 1.f / (1.f + __expf(-c[1]));
  float s2 = 1.f / (1.f + __expf(-c[2]));
  float s3 = 1.f / (1.f + __expf(-c[3]));
  g_stg[b * 16384 + row0 * 256 + cg] = As[row0 * MP + cg] + s0 * estate[row0 * 256 + cg];
  g_stg[b * 16384 + row0 * 256 + cg + 1] = As[row0 * MP + cg + 1] + s1 * estate[row0 * 256 + cg + 1];
  g_stg[b * 16384 + row1 * 256 + cg] = As[row1 * MP + cg] + s2 * estate[row1 * 256 + cg];
  g_stg[b * 16384 + row1 * 256 + cg + 1] = As[row1 * MP + cg + 1] + s3 * estate[row1 * 256 + cg + 1];
}

__global__ __launch_bounds__(512) void k_qkv(
    const float* __restrict__ in_w, const float* __restrict__ in_b) {
  extern __shared__ float smm[];
  float* As = smm;
  float* ws = smm + 64 * MP;
  MID_PROLOG
  stage_mid(As, ws, g_stg + b * 16384, 256, in_w, 256, c0, 0, tid);
  float b0v = in_b[cg], b1v = in_b[cg + 1];
  float c[4] = {b0v, b1v, b0v, b1v};
  __syncthreads();
  mid_mma(As, ws, c, mA, nq, r, q);
  g_qkv[(b * 64 + row0) * 768 + cg] = c[0];
  g_qkv[(b * 64 + row0) * 768 + cg + 1] = c[1];
  g_qkv[(b * 64 + row1) * 768 + cg] = c[2];
  g_qkv[(b * 64 + row1) * 768 + cg + 1] = c[3];
}

// attention per (b, head): 32 blocks, 1024 threads
__global__ __launch_bounds__(1024) void k_attn() {
  int b = blockIdx.x >> 3, hh = blockIdx.x & 7;
  __shared__ float q[64][32], kk[64][33], vv[64][32], p[64][65];
  int tid = threadIdx.x;
  for (int i = tid; i < 2048; i += 1024) {
    int s = i >> 5, d = i & 31;
    int base = (b * 64 + s) * 768 + hh * 32 + d;
    q[s][d] = g_qkv[base];
    kk[s][d] = g_qkv[base + 256];
    vv[s][d] = g_qkv[base + 512];
  }
  __syncthreads();
  for (int idx = tid; idx < 4096; idx += 1024) {
    int qi = idx >> 6, ki = idx & 63;
    float a = 0.f;
#pragma unroll
    for (int d = 0; d < 32; d++) a += q[qi][d] * kk[ki][d];
    p[qi][ki] = a * 0.17677669529663687f;
  }
  __syncthreads();
  if (tid < 512) {
    const int row = tid >> 3, qq = tid & 7;
    float v[8], mx = -1e30f;
#pragma unroll
    for (int i = 0; i < 8; i++) {
      v[i] = p[row][qq * 8 + i];
      mx = fmaxf(mx, v[i]);
    }
    mx = fmaxf(mx, __shfl_xor_sync(0xffffffffu, mx, 1));
    mx = fmaxf(mx, __shfl_xor_sync(0xffffffffu, mx, 2));
    mx = fmaxf(mx, __shfl_xor_sync(0xffffffffu, mx, 4));
    float s = 0.f;
#pragma unroll
    for (int i = 0; i < 8; i++) { v[i] = __expf(v[i] - mx); s += v[i]; }
    s += __shfl_xor_sync(0xffffffffu, s, 1);
    s += __shfl_xor_sync(0xffffffffu, s, 2);
    s += __shfl_xor_sync(0xffffffffu, s, 4);
    const float inv = 1.f / s;
#pragma unroll
    for (int i = 0; i < 8; i++) p[row][qq * 8 + i] = v[i] * inv;
  }
  __syncthreads();
  for (int idx = tid; idx < 2048; idx += 1024) {
    int qi = idx >> 5, d = idx & 31;
    float a = 0.f;
#pragma unroll
    for (int j = 0; j < 64; j++) a += p[qi][j] * vv[j][d];
    g_ao[(b * 64 + qi) * 256 + hh * 32 + d] = a;
  }
}

__global__ __launch_bounds__(512) void k_proj(
    const float* __restrict__ out_w, const float* __restrict__ out_b) {
  extern __shared__ float smm[];
  float* As = smm;
  float* ws = smm + 64 * MP;
  MID_PROLOG
  stage_mid(As, ws, g_ao + b * 16384, 256, out_w, 256, c0, 0, tid);
  float b0v = out_b[cg], b1v = out_b[cg + 1];
  float c[4] = {b0v, b1v, b0v, b1v};
  __syncthreads();
  mid_mma(As, ws, c, mA, nq, r, q);
  g_pro[(b * 64 + row0) * 256 + cg] = c[0];
  g_pro[(b * 64 + row0) * 256 + cg + 1] = c[1];
  g_pro[(b * 64 + row1) * 256 + cg] = c[2];
  g_pro[(b * 64 + row1) * 256 + cg + 1] = c[3];
}

// LN: out = LN(a + sum of np partials)
__device__ __forceinline__ void ln4_reduce(float yv[4], float mu[4], float var[4],
                                           float wsum[4][8], float wsq[4][8],
                                           int tid) {
  float s1[4], s2[4];
#pragma unroll
  for (int r = 0; r < 4; r++) { s1[r] = yv[r]; s2[r] = yv[r] * yv[r]; }
#pragma unroll
  for (int off = 16; off; off >>= 1)
#pragma unroll
    for (int r = 0; r < 4; r++) {
      s1[r] += __shfl_xor_sync(0xffffffffu, s1[r], off);
      s2[r] += __shfl_xor_sync(0xffffffffu, s2[r], off);
    }
  int w = tid >> 5, lane = tid & 31;
  if (lane == 0)
#pragma unroll
    for (int r = 0; r < 4; r++) { wsum[r][w] = s1[r]; wsq[r][w] = s2[r]; }
  __syncthreads();
#pragma unroll
  for (int r = 0; r < 4; r++) {
    float a = 0.f, bq = 0.f;
#pragma unroll
    for (int ww = 0; ww < 8; ww++) { a += wsum[r][ww]; bq += wsq[r][ww]; }
    mu[r] = a * (1.f / 256.f);
    var[r] = bq * (1.f / 256.f) - mu[r] * mu[r];
  }
}

__global__ __launch_bounds__(256) void k_ln(
    const float* __restrict__ a, const float* __restrict__ parts, int np,
    const float* __restrict__ g, const float* __restrict__ bb,
    float* __restrict__ out) {
  int bs0 = blockIdx.x * 4;
  __shared__ float wsum[4][8], wsq[4][8];
  int tid = threadIdx.x;
  float yv[4];
#pragma unroll
  for (int r = 0; r < 4; r++) {
    int idx = (bs0 + r) * 256 + tid;
    float v = a[idx];
    for (int pz = 0; pz < np; pz++) v += parts[pz * (BB * SS * HH) + idx];
    yv[r] = v;
  }
  float mu[4], var[4];
  ln4_reduce(yv, mu, var, wsum, wsq, tid);
#pragma unroll
  for (int r = 0; r < 4; r++)
    out[(bs0 + r) * 256 + tid] =
        (yv[r] - mu[r]) * rsqrtf(var[r] + 1e-5f) * g[tid] + bb[tid];
}

// ffn1: 1024 outputs, GELU
__global__ __launch_bounds__(512) void k_ffn1(
    const float* __restrict__ f1_w, const float* __restrict__ f1_b) {
  extern __shared__ float smm[];
  float* As = smm;
  float* ws = smm + 64 * MP;
  MID_PROLOG
  stage_mid(As, ws, g_st1 + b * 16384, 256, f1_w, 256, c0, 0, tid);
  float b0v = f1_b[cg], b1v = f1_b[cg + 1];
  float c[4] = {b0v, b1v, b0v, b1v};
  __syncthreads();
  mid_mma(As, ws, c, mA, nq, r, q);
#pragma unroll
  for (int j = 0; j < 4; j++) {
    float v = c[j];
    c[j] = 0.5f * v * (1.f + erff(v * 0.7071067811865475f));
  }
  g_h[(b * 64 + row0) * 1024 + cg] = c[0];
  g_h[(b * 64 + row0) * 1024 + cg + 1] = c[1];
  g_h[(b * 64 + row1) * 1024 + cg] = c[2];
  g_h[(b * 64 + row1) * 1024 + cg + 1] = c[3];
}

// ffn2: K=1024 with 4-way k-split (blockIdx.z)
__global__ __launch_bounds__(512) void k_ffn2(
    const float* __restrict__ f2_w, const float* __restrict__ f2_b) {
  extern __shared__ float smm[];
  float* As = smm;
  float* ws = smm + 64 * MP;
  const int z = blockIdx.z;
  MID_PROLOG
  stage_mid(As, ws, g_h + b * 65536 + z * 256, 1024, f2_w, 1024, c0, z * 256,
            tid);
  float b0v = (z == 0) ? f2_b[cg] : 0.f;
  float b1v = (z == 0) ? f2_b[cg + 1] : 0.f;
  float c[4] = {b0v, b1v, b0v, b1v};
  __syncthreads();
  mid_mma(As, ws, c, mA, nq, r, q);
  g_f2p[z][(b * 64 + row0) * 256 + cg] = c[0];
  g_f2p[z][(b * 64 + row0) * 256 + cg + 1] = c[1];
  g_f2p[z][(b * 64 + row1) * 256 + cg] = c[2];
  g_f2p[z][(b * 64 + row1) * 256 + cg + 1] = c[3];
}

// ===========================================================================
// KC: decode out = W @ st2 + x via tf32 mma. 512 threads, 256 tokens/block.
// ===========================================================================
__global__ __launch_bounds__(512) void k_decode(const float* __restrict__ x,
                                                float* __restrict__ out) {
  extern __shared__ float sm[];
  float* st2s = sm;              // [64][SP]
  float* Ws = sm + 64 * SP;      // [256][AP]
  const int tid = threadIdx.x;
  const int b = blockIdx.y;
  const int n0 = blockIdx.x * 256;

  for (int i = tid * 4; i < 16384; i += 2048)
    *(float4*)(st2s + (i >> 8) * SP + (i & 255)) =
        *(const float4*)(g_st2 + b * 16384 + i);
  for (int i = tid * 4; i < 16384; i += 2048)
    *(float4*)(Ws + (i >> 6) * AP + (i & 63)) =
        *(const float4*)(g_W + ((size_t)b * NN + n0 + (i >> 6)) * 64 + (i & 63));
  __syncthreads();

  const int wid = tid >> 5, lane = tid & 31;
  const int r = lane >> 2, q = lane & 3;
  const int m0 = wid * 16;

  for (int nh = 0; nh < 2; nh++) {
    float acc[16][4];
#pragma unroll
    for (int i = 0; i < 16; i++)
#pragma unroll
      for (int j = 0; j < 4; j++) acc[i][j] = 0.f;

    for (int ks = 0; ks < 8; ks++) {
      const int k0 = ks * 8;
      uint32_t a0 = F2U(Ws[(m0 + r) * AP + k0 + q]);
      uint32_t a1 = F2U(Ws[(m0 + r + 8) * AP + k0 + q]);
      uint32_t a2 = F2U(Ws[(m0 + r) * AP + k0 + q + 4]);
      uint32_t a3 = F2U(Ws[(m0 + r + 8) * AP + k0 + q + 4]);
#pragma unroll
      for (int nt = 0; nt < 16; nt++) {
        const int n = nh * 128 + nt * 8;
        uint32_t b0 = F2U(st2s[(k0 + q) * SP + n + r]);
        uint32_t b1 = F2U(st2s[(k0 + q + 4) * SP + n + r]);
        mma_tf32(acc[nt], a0, a1, a2, a3, b0, b1);
      }
    }
#pragma unroll
    for (int nt = 0; nt < 16; nt++) {
      const int n = nh * 128 + nt * 8 + 2 * q;
      const size_t base0 = ((size_t)b * NN + n0 + m0 + r) * 256 + n;
      const size_t base1 = base0 + 8 * 256;
      float2 xv0 = *(const float2*)(x + base0);
      float2 xv1 = *(const float2*)(x + base1);
      *(float2*)(out + base0) = make_float2(acc[nt][0] + xv0.x, acc[nt][1] + xv0.y);
      *(float2*)(out + base1) = make_float2(acc[nt][2] + xv1.x, acc[nt][3] + xv1.y);
    }
  }
}

// ===========================================================================
extern "C" void kernel_launch(void* const* d_in, const int* in_sizes, int n_in,
                              void* d_out, int out_size) {
  const float* x = (const float*)d_in[0];
  const float* sq_w = (const float*)d_in[1];
  const float* sq_b = (const float*)d_in[2];
  const float* eid_state = (const float*)d_in[3];
  const float* eid_gw = (const float*)d_in[4];
  const float* eid_gb = (const float*)d_in[5];
  const float* in_w = (const float*)d_in[6];
  const float* in_b = (const float*)d_in[7];
  const float* out_w = (const float*)d_in[8];
  const float* out_b = (const float*)d_in[9];
  const float* n1_g = (const float*)d_in[10];
  const float* n1_b = (const float*)d_in[11];
  const float* n2_g = (const float*)d_in[12];
  const float* n2_b = (const float*)d_in[13];
  const float* f1_w = (const float*)d_in[14];
  const float* f1_b = (const float*)d_in[15];
  const float* f2_w = (const float*)d_in[16];
  const float* f2_b = (const float*)d_in[17];
  float* out = (float*)d_out;

  const int smem_ka = (64 * XP + 64 * WP + 64 * LP + 64) * 4;
  const int smem_kc = (64 * SP + 256 * AP) * 4;
  cudaFuncSetAttribute(k_assign_pool, cudaFuncAttributeMaxDynamicSharedMemorySize, smem_ka);
  cudaFuncSetAttribute(k_decode, cudaFuncAttributeMaxDynamicSharedMemorySize, smem_kc);
  cudaFuncSetAttribute(k_gate, cudaFuncAttributeMaxDynamicSharedMemorySize, MIDQ_SMEM);
  cudaFuncSetAttribute(k_qkv, cudaFuncAttributeMaxDynamicSharedMemorySize, MIDQ_SMEM);
  cudaFuncSetAttribute(k_proj, cudaFuncAttributeMaxDynamicSharedMemorySize, MIDQ_SMEM);
  cudaFuncSetAttribute(k_ffn1, cudaFuncAttributeMaxDynamicSharedMemorySize, MIDQ_SMEM);
  cudaFuncSetAttribute(k_ffn2, cudaFuncAttributeMaxDynamicSharedMemorySize, MIDQ_SMEM);

  float *p_stg, *p_pro, *p_st1, *p_f2p, *p_st2;
  cudaGetSymbolAddress((void**)&p_stg, g_stg);
  cudaGetSymbolAddress((void**)&p_pro, g_pro);
  cudaGetSymbolAddress((void**)&p_st1, g_st1);
  cudaGetSymbolAddress((void**)&p_f2p, g_f2p);
  cudaGetSymbolAddress((void**)&p_st2, g_st2);

  k_assign_pool<<<dim3(64, BB), 512, smem_ka>>>(x, sq_w, sq_b);
  k_reduce_st<<<64, 256>>>();
  k_gate<<<dim3(8, BB), 512, MIDQ_SMEM>>>(eid_gw, eid_gb, eid_state);
  k_qkv<<<dim3(24, BB), 512, MIDQ_SMEM>>>(in_w, in_b);
  k_attn<<<32, 1024>>>();
  k_proj<<<dim3(8, BB), 512, MIDQ_SMEM>>>(out_w, out_b);
  k_ln<<<64, 256>>>(p_stg, p_pro, 1, n1_g, n1_b, p_st1);
  k_ffn1<<<dim3(32, BB), 512, MIDQ_SMEM>>>(f1_w, f1_b);
  k_ffn2<<<dim3(8, BB, 4), 512, MIDQ_SMEM>>>(f2_w, f2_b);
  k_ln<<<64, 256>>>(p_st1, p_f2p, 4, n2_g, n2_b, p_st2);
  k_decode<<<dim3(128, BB), 512, smem_kc>>>(x, out);
}